// round 2
// baseline (speedup 1.0000x reference)
#include <cuda_runtime.h>

// ---------------------------------------------------------------------------
// MultiHeadSelfAttention with relative position scores.
// B=4, T=1024, H=8, D=64, N_UNITS=512.
//
// Pipeline:
//   K1 (x3): proj = x @ W + b   -> Q/K/V scratch in [b][h][t][d] layout
//   K2     : S_pos[q][bh][k] = Q[bh,q,:] . pos_k[q,k,:]   (pos read once)
//   K3     : flash attention per (bh, q-tile): S = (QK^T + S_pos)/8,
//            online softmax, O += P V
//   K4     : out = O_flat @ Wo + bo
// ---------------------------------------------------------------------------

#define NBH 32      // B*H
#define TSEQ 1024
#define DHEAD 64

__device__ __align__(16) float g_Q[NBH * TSEQ * DHEAD];
__device__ __align__(16) float g_K[NBH * TSEQ * DHEAD];
__device__ __align__(16) float g_V[NBH * TSEQ * DHEAD];
__device__ __align__(16) float g_O[4096 * 512];
__device__ __align__(16) float g_Spos[TSEQ * NBH * TSEQ];   // [q][bh][k], 128 MB

// ---------------------------------------------------------------------------
// K1/K4: M=4096, N=512, K=512 GEMM, 128x64 block tile, 8x4 micro tile.
// permute=1 -> store to [b][h][t][d] layout (QKV); permute=0 -> row-major.
// ---------------------------------------------------------------------------
__global__ __launch_bounds__(256) void gemm512_kernel(
    const float* __restrict__ A, const float* __restrict__ W,
    const float* __restrict__ bias, float* __restrict__ out, int permute)
{
    __shared__ __align__(16) float As[16][132];   // [k][m]
    __shared__ __align__(16) float Bs[16][68];    // [k][n]

    const int tid  = threadIdx.x;
    const int tm0  = (tid >> 4) << 3;     // 0..120 step 8
    const int tn0  = (tid & 15) << 2;     // 0..60 step 4
    const int mbase = blockIdx.y * 128;
    const int nbase = blockIdx.x * 64;

    const int lm = tid >> 2;              // 0..63
    const int lk = (tid & 3) << 2;        // 0,4,8,12
    const int bk = tid >> 4;              // 0..15
    const int bn = (tid & 15) << 2;       // 0..60

    float acc[8][4];
#pragma unroll
    for (int i = 0; i < 8; i++)
#pragma unroll
        for (int j = 0; j < 4; j++) acc[i][j] = 0.f;

    for (int k0 = 0; k0 < 512; k0 += 16) {
#pragma unroll
        for (int i = 0; i < 2; i++) {
            int m = lm + i * 64;
            float4 v = *(const float4*)(A + (size_t)(mbase + m) * 512 + k0 + lk);
            As[lk + 0][m] = v.x; As[lk + 1][m] = v.y;
            As[lk + 2][m] = v.z; As[lk + 3][m] = v.w;
        }
        {
            float4 v = *(const float4*)(W + (size_t)(k0 + bk) * 512 + nbase + bn);
            *(float4*)&Bs[bk][bn] = v;
        }
        __syncthreads();
#pragma unroll
        for (int k = 0; k < 16; k++) {
            float4 a0 = *(float4*)&As[k][tm0];
            float4 a1 = *(float4*)&As[k][tm0 + 4];
            float4 b4 = *(float4*)&Bs[k][tn0];
            float av[8] = {a0.x, a0.y, a0.z, a0.w, a1.x, a1.y, a1.z, a1.w};
            float bv[4] = {b4.x, b4.y, b4.z, b4.w};
#pragma unroll
            for (int i = 0; i < 8; i++)
#pragma unroll
                for (int j = 0; j < 4; j++)
                    acc[i][j] = fmaf(av[i], bv[j], acc[i][j]);
        }
        __syncthreads();
    }

    float4 bb = *(const float4*)(bias + nbase + tn0);
    const float bvv[4] = {bb.x, bb.y, bb.z, bb.w};

    if (permute) {
        const int h = nbase >> 6;   // N tile = 64 = head dim, so h == blockIdx.x
#pragma unroll
        for (int i = 0; i < 8; i++) {
            int m = mbase + tm0 + i;
            int b_ = m >> 10, t = m & 1023;
            float4 o = make_float4(acc[i][0] + bvv[0], acc[i][1] + bvv[1],
                                   acc[i][2] + bvv[2], acc[i][3] + bvv[3]);
            *(float4*)(out + (((size_t)(b_ * 8 + h) * 1024 + t) << 6) + tn0) = o;
        }
    } else {
#pragma unroll
        for (int i = 0; i < 8; i++) {
            int m = mbase + tm0 + i;
            float4 o = make_float4(acc[i][0] + bvv[0], acc[i][1] + bvv[1],
                                   acc[i][2] + bvv[2], acc[i][3] + bvv[3]);
            *(float4*)(out + (size_t)m * 512 + nbase + tn0) = o;
        }
    }
}

// ---------------------------------------------------------------------------
// K2: per query position q, S_pos[bh, k] = Q[bh, q, :] . pos_k[q, k, :]
// GEMM M=32 (bh), N=128 (k block), K=64 (d). grid = (k-blocks=8, q=1024)
// pos_k is read exactly once from HBM; each value reused 32x via smem.
// ---------------------------------------------------------------------------
__global__ __launch_bounds__(256) void pos_score_kernel(const float* __restrict__ pos_k)
{
    __shared__ __align__(16) float Qt[64][36];    // [d][bh]
    __shared__ __align__(16) float Pt[64][132];   // [d][k]

    const int q   = blockIdx.y;
    const int kb  = blockIdx.x;        // * 128
    const int tid = threadIdx.x;

#pragma unroll
    for (int i = 0; i < 2; i++) {
        int f  = tid + i * 256;
        int bh = f >> 4;
        int d4 = (f & 15) << 2;
        float4 v = *(const float4*)(g_Q + (((size_t)bh * 1024 + q) << 6) + d4);
        Qt[d4 + 0][bh] = v.x; Qt[d4 + 1][bh] = v.y;
        Qt[d4 + 2][bh] = v.z; Qt[d4 + 3][bh] = v.w;
    }
#pragma unroll
    for (int i = 0; i < 8; i++) {
        int f  = tid + i * 256;
        int kk = f >> 4;
        int d4 = (f & 15) << 2;
        float4 v = *(const float4*)(pos_k + (((size_t)q * 1024 + kb * 128 + kk) << 6) + d4);
        Pt[d4 + 0][kk] = v.x; Pt[d4 + 1][kk] = v.y;
        Pt[d4 + 2][kk] = v.z; Pt[d4 + 3][kk] = v.w;
    }
    __syncthreads();

    const int tbh = (tid >> 5) << 2;   // 0..28 step 4
    const int tk  = (tid & 31) << 2;   // 0..124 step 4

    float acc[4][4];
#pragma unroll
    for (int i = 0; i < 4; i++)
#pragma unroll
        for (int j = 0; j < 4; j++) acc[i][j] = 0.f;

#pragma unroll 4
    for (int d = 0; d < 64; d++) {
        float4 a = *(float4*)&Qt[d][tbh];   // broadcast within warp
        float4 b = *(float4*)&Pt[d][tk];
        float av[4] = {a.x, a.y, a.z, a.w};
        float bv[4] = {b.x, b.y, b.z, b.w};
#pragma unroll
        for (int i = 0; i < 4; i++)
#pragma unroll
            for (int j = 0; j < 4; j++)
                acc[i][j] = fmaf(av[i], bv[j], acc[i][j]);
    }

#pragma unroll
    for (int i = 0; i < 4; i++) {
        *(float4*)(g_Spos + ((size_t)q * 32 + tbh + i) * 1024 + kb * 128 + tk) =
            make_float4(acc[i][0], acc[i][1], acc[i][2], acc[i][3]);
    }
}

// ---------------------------------------------------------------------------
// K3: flash attention. One CTA = (bh, 64-query tile). 16 key tiles of 64.
// smem: Qs[64][68], Kt[64][68] (transposed), Vs[64][68], Ss[64][68] + state.
// ---------------------------------------------------------------------------
#define ATTN_SMEM_FLOATS (4 * 64 * 68 + 3 * 64 + 256)

__global__ __launch_bounds__(256) void attn_kernel()
{
    extern __shared__ __align__(16) float sm[];
    float* Qs   = sm;                  // [q][d] stride 68
    float* Kt   = sm + 64 * 68;        // [d][k] stride 68
    float* Vs   = sm + 2 * 64 * 68;    // [k][d] stride 68
    float* Ss   = sm + 3 * 64 * 68;    // [q][k] stride 68 (scores, then P)
    float* mrow = sm + 4 * 64 * 68;    // 64
    float* lrow = mrow + 64;           // 64
    float* corr = lrow + 64;           // 64
    float* red  = corr + 64;           // [64][4]

    const int tid = threadIdx.x;
    const int bh  = blockIdx.y;
    const int qt  = blockIdx.x;
    const int b_  = bh >> 3;
    const int h   = bh & 7;

    const int lr  = tid >> 4;          // 0..15 (load row group)
    const int ld4 = (tid & 15) << 2;   // 0..60

    const size_t baseQ = ((size_t)bh * 1024 + qt * 64) << 6;
#pragma unroll
    for (int i = 0; i < 4; i++) {
        int r = lr + i * 16;
        float4 v = *(const float4*)(g_Q + baseQ + ((size_t)r << 6) + ld4);
        *(float4*)&Qs[r * 68 + ld4] = v;
    }
    if (tid < 64) { mrow[tid] = -1e30f; lrow[tid] = 0.f; }

    const int q0 = (tid >> 4) << 2;    // 0..60
    const int x0 = (tid & 15) << 2;    // 0..60  (k in S phase, d in PV phase)
    const int sr = tid >> 2;           // softmax row 0..63
    const int sc = tid & 3;            // softmax col group

    float acco[4][4];
#pragma unroll
    for (int i = 0; i < 4; i++)
#pragma unroll
        for (int j = 0; j < 4; j++) acco[i][j] = 0.f;
    __syncthreads();

    for (int kt = 0; kt < 16; kt++) {
        const size_t baseK = ((size_t)bh * 1024 + kt * 64) << 6;
#pragma unroll
        for (int i = 0; i < 4; i++) {
            int r = lr + i * 16;
            float4 kv = *(const float4*)(g_K + baseK + ((size_t)r << 6) + ld4);
            Kt[(ld4 + 0) * 68 + r] = kv.x;
            Kt[(ld4 + 1) * 68 + r] = kv.y;
            Kt[(ld4 + 2) * 68 + r] = kv.z;
            Kt[(ld4 + 3) * 68 + r] = kv.w;
            float4 vv = *(const float4*)(g_V + baseK + ((size_t)r << 6) + ld4);
            *(float4*)&Vs[r * 68 + ld4] = vv;
        }
        __syncthreads();

        // ---- S = Q K^T ----
        float acc[4][4];
#pragma unroll
        for (int i = 0; i < 4; i++)
#pragma unroll
            for (int j = 0; j < 4; j++) acc[i][j] = 0.f;
#pragma unroll 4
        for (int d = 0; d < 64; d++) {
            float4 kv = *(float4*)&Kt[d * 68 + x0];
            float kvv[4] = {kv.x, kv.y, kv.z, kv.w};
#pragma unroll
            for (int i = 0; i < 4; i++) {
                float a = Qs[(q0 + i) * 68 + d];   // warp broadcast
#pragma unroll
                for (int j = 0; j < 4; j++)
                    acc[i][j] = fmaf(a, kvv[j], acc[i][j]);
            }
        }
        // add pos scores + scale, store to smem
#pragma unroll
        for (int i = 0; i < 4; i++) {
            float4 sp = *(const float4*)(g_Spos +
                ((size_t)(qt * 64 + q0 + i) * 32 + bh) * 1024 + kt * 64 + x0);
            float4 s = make_float4((acc[i][0] + sp.x) * 0.125f,
                                   (acc[i][1] + sp.y) * 0.125f,
                                   (acc[i][2] + sp.z) * 0.125f,
                                   (acc[i][3] + sp.w) * 0.125f);
            *(float4*)&Ss[(q0 + i) * 68 + x0] = s;
        }
        __syncthreads();

        // ---- online softmax (4 threads per row) ----
        float pm = -1e30f;
        {
            const float* srow = &Ss[sr * 68 + sc * 16];
#pragma unroll
            for (int j = 0; j < 16; j++) pm = fmaxf(pm, srow[j]);
        }
        red[sr * 4 + sc] = pm;
        __syncthreads();
        float mold = mrow[sr];
        float mn = fmaxf(fmaxf(red[sr * 4 + 0], red[sr * 4 + 1]),
                         fmaxf(red[sr * 4 + 2], red[sr * 4 + 3]));
        mn = fmaxf(mn, mold);
        __syncthreads();   // protect red[] reuse + mrow reads
        float ps = 0.f;
        {
            float* prow = &Ss[sr * 68 + sc * 16];
#pragma unroll
            for (int j = 0; j < 16; j++) {
                float p = __expf(prow[j] - mn);
                prow[j] = p;
                ps += p;
            }
        }
        red[sr * 4 + sc] = ps;
        __syncthreads();
        if (sc == 0) {
            float s4 = red[sr * 4 + 0] + red[sr * 4 + 1] +
                       red[sr * 4 + 2] + red[sr * 4 + 3];
            float cr = __expf(mold - mn);
            lrow[sr] = lrow[sr] * cr + s4;
            mrow[sr] = mn;
            corr[sr] = cr;
        }
        __syncthreads();

        // ---- O = O*corr + P V ----
#pragma unroll
        for (int i = 0; i < 4; i++) {
            float cr = corr[q0 + i];
            acco[i][0] *= cr; acco[i][1] *= cr;
            acco[i][2] *= cr; acco[i][3] *= cr;
        }
#pragma unroll 4
        for (int k = 0; k < 64; k++) {
            float4 vv = *(float4*)&Vs[k * 68 + x0];
            float vvv[4] = {vv.x, vv.y, vv.z, vv.w};
#pragma unroll
            for (int i = 0; i < 4; i++) {
                float p = Ss[(q0 + i) * 68 + k];   // warp broadcast
#pragma unroll
                for (int j = 0; j < 4; j++)
                    acco[i][j] = fmaf(p, vvv[j], acco[i][j]);
            }
        }
        __syncthreads();
    }

#pragma unroll
    for (int i = 0; i < 4; i++) {
        float inv = 1.f / lrow[q0 + i];
        int qg = qt * 64 + q0 + i;
        float4 o = make_float4(acco[i][0] * inv, acco[i][1] * inv,
                               acco[i][2] * inv, acco[i][3] * inv);
        *(float4*)(g_O + (size_t)(b_ * 1024 + qg) * 512 + (h << 6) + x0) = o;
    }
}

// ---------------------------------------------------------------------------
// launch
// ---------------------------------------------------------------------------
extern "C" void kernel_launch(void* const* d_in, const int* in_sizes, int n_in,
                              void* d_out, int out_size)
{
    (void)in_sizes; (void)n_in; (void)out_size;
    const float* x    = (const float*)d_in[0];
    const float* posk = (const float*)d_in[1];
    // d_in[2] = batch_size (constant 4), ignored
    const float* Wq = (const float*)d_in[3];
    const float* bq = (const float*)d_in[4];
    const float* Wk = (const float*)d_in[5];
    const float* bk = (const float*)d_in[6];
    const float* Wv = (const float*)d_in[7];
    const float* bv = (const float*)d_in[8];
    const float* Wo = (const float*)d_in[9];
    const float* bo = (const float*)d_in[10];
    float* out = (float*)d_out;

    float *qp, *kp, *vp, *op;
    cudaGetSymbolAddress((void**)&qp, g_Q);
    cudaGetSymbolAddress((void**)&kp, g_K);
    cudaGetSymbolAddress((void**)&vp, g_V);
    cudaGetSymbolAddress((void**)&op, g_O);

    const int attn_smem = ATTN_SMEM_FLOATS * 4;
    cudaFuncSetAttribute(attn_kernel,
                         cudaFuncAttributeMaxDynamicSharedMemorySize, attn_smem);

    dim3 gproj(8, 32);   // N/64, M/128
    gemm512_kernel<<<gproj, 256>>>(x, Wq, bq, qp, 1);
    gemm512_kernel<<<gproj, 256>>>(x, Wk, bk, kp, 1);
    gemm512_kernel<<<gproj, 256>>>(x, Wv, bv, vp, 1);

    pos_score_kernel<<<dim3(8, 1024), 256>>>(posk);

    attn_kernel<<<dim3(16, 32), 256, attn_smem>>>();

    gemm512_kernel<<<gproj, 256>>>(op, Wo, bo, out, 0);
}

// round 3
// speedup vs baseline: 2.0579x; 2.0579x over previous
#include <cuda_runtime.h>

// ---------------------------------------------------------------------------
// MultiHeadSelfAttention with relative position scores — TF32 tensor cores.
// B=4, T=1024, H=8, D=64, N_UNITS=512.
//
//   K1: fused QKV projection (mma tf32), out in [bh][t][d]
//   K2: S_pos[bh][q][k] = Q[bh,q,:] . pos_k[q,k,:]  (mma tf32, pos read once)
//   K3: flash attention (QK^T + Spos)/8, online softmax, P.V — all mma tf32,
//       P reused from C-fragments (pi-permuted k makes C layout == A layout)
//   K4: output projection (mma tf32)
// ---------------------------------------------------------------------------

#define NBH 32
#define TSEQ 1024
#define DH 64

__device__ __align__(16) float g_Q[NBH * TSEQ * DH];
__device__ __align__(16) float g_K[NBH * TSEQ * DH];
__device__ __align__(16) float g_V[NBH * TSEQ * DH];
__device__ __align__(16) float g_O[4096 * 512];
__device__ __align__(16) float g_Spos[(size_t)NBH * TSEQ * TSEQ];  // [bh][q][k]

__device__ __forceinline__ unsigned cvt_tf32(float x) {
    unsigned u; asm("cvt.rna.tf32.f32 %0, %1;" : "=r"(u) : "f"(x)); return u;
}
__device__ __forceinline__ float cvt_tf32f(float x) {
    return __uint_as_float(cvt_tf32(x));
}
__device__ __forceinline__ void mma8(float* c, const unsigned* a,
                                     unsigned b0, unsigned b1) {
    asm volatile(
        "mma.sync.aligned.m16n8k8.row.col.f32.tf32.tf32.f32 "
        "{%0,%1,%2,%3}, {%4,%5,%6,%7}, {%8,%9}, {%0,%1,%2,%3};\n"
        : "+f"(c[0]), "+f"(c[1]), "+f"(c[2]), "+f"(c[3])
        : "r"(a[0]), "r"(a[1]), "r"(a[2]), "r"(a[3]), "r"(b0), "r"(b1));
}

// ---------------------------------------------------------------------------
// GEMM body: M=4096, N=512, K=512. CTA 128x128, 8 warps, warp tile 32x64.
// A row-major [m][k]; B staged transposed [n][k] (pi-permuted k => float2 ldS).
// ---------------------------------------------------------------------------
__device__ __forceinline__ void gemm_body(
    const float* __restrict__ A, const float* __restrict__ W,
    const float* __restrict__ bias, float* __restrict__ out, int permute)
{
    __shared__ float As[128 * 40];
    __shared__ float Bs[128 * 40];
    const int tid  = threadIdx.x;
    const int lane = tid & 31;
    const int g    = lane >> 2, tig = lane & 3;
    const int warp = tid >> 5;
    const int wm   = warp >> 1, wn = warp & 1;
    const int mbase = blockIdx.y * 128, nbase = blockIdx.x * 128;

    float C[2][8][4];
#pragma unroll
    for (int mb = 0; mb < 2; mb++)
#pragma unroll
        for (int nb = 0; nb < 8; nb++)
#pragma unroll
            for (int i = 0; i < 4; i++) C[mb][nb][i] = 0.f;

    for (int k0 = 0; k0 < 512; k0 += 32) {
#pragma unroll
        for (int i = 0; i < 4; i++) {
            int j = tid + i * 256;
            int m = j >> 3, k4 = (j & 7) << 2;
            float4 v = *(const float4*)(A + (size_t)(mbase + m) * 512 + k0 + k4);
            float* d = &As[m * 40 + k4];
            d[0] = cvt_tf32f(v.x); d[1] = cvt_tf32f(v.y);
            d[2] = cvt_tf32f(v.z); d[3] = cvt_tf32f(v.w);
        }
#pragma unroll
        for (int i = 0; i < 4; i++) {
            int j = tid + i * 256;
            int kk = j & 31, n0 = (j >> 5) << 2;
            float4 v = *(const float4*)(W + (size_t)(k0 + kk) * 512 + nbase + n0);
            Bs[(n0 + 0) * 40 + kk] = cvt_tf32f(v.x);
            Bs[(n0 + 1) * 40 + kk] = cvt_tf32f(v.y);
            Bs[(n0 + 2) * 40 + kk] = cvt_tf32f(v.z);
            Bs[(n0 + 3) * 40 + kk] = cvt_tf32f(v.w);
        }
        __syncthreads();
#pragma unroll
        for (int kk = 0; kk < 4; kk++) {
            unsigned a[2][4];
#pragma unroll
            for (int mb = 0; mb < 2; mb++) {
                int r = wm * 32 + mb * 16 + g;
                float2 t0 = *(float2*)&As[r * 40 + kk * 8 + 2 * tig];
                float2 t1 = *(float2*)&As[(r + 8) * 40 + kk * 8 + 2 * tig];
                a[mb][0] = __float_as_uint(t0.x);
                a[mb][2] = __float_as_uint(t0.y);
                a[mb][1] = __float_as_uint(t1.x);
                a[mb][3] = __float_as_uint(t1.y);
            }
#pragma unroll
            for (int nb = 0; nb < 8; nb++) {
                float2 tb = *(float2*)&Bs[(wn * 64 + nb * 8 + g) * 40 + kk * 8 + 2 * tig];
                unsigned b0 = __float_as_uint(tb.x), b1 = __float_as_uint(tb.y);
                mma8(C[0][nb], a[0], b0, b1);
                mma8(C[1][nb], a[1], b0, b1);
            }
        }
        __syncthreads();
    }

#pragma unroll
    for (int nb = 0; nb < 8; nb++) {
        int ncol = wn * 64 + nb * 8 + 2 * tig;
        float2 bb = *(const float2*)(bias + nbase + ncol);
#pragma unroll
        for (int mb = 0; mb < 2; mb++) {
            int r0 = mbase + wm * 32 + mb * 16 + g;
            int r1 = r0 + 8;
            float2 v0 = make_float2(C[mb][nb][0] + bb.x, C[mb][nb][1] + bb.y);
            float2 v1 = make_float2(C[mb][nb][2] + bb.x, C[mb][nb][3] + bb.y);
            if (permute) {
                int h = (nbase >> 6) + wn;
                int d = nb * 8 + 2 * tig;
                *(float2*)(out + (((size_t)((r0 >> 10) * 8 + h) * 1024 + (r0 & 1023)) << 6) + d) = v0;
                *(float2*)(out + (((size_t)((r1 >> 10) * 8 + h) * 1024 + (r1 & 1023)) << 6) + d) = v1;
            } else {
                *(float2*)(out + (size_t)r0 * 512 + nbase + ncol) = v0;
                *(float2*)(out + (size_t)r1 * 512 + nbase + ncol) = v1;
            }
        }
    }
}

__global__ __launch_bounds__(256) void qkv_kernel(
    const float* __restrict__ x,
    const float* __restrict__ Wq, const float* __restrict__ bq,
    const float* __restrict__ Wk, const float* __restrict__ bk,
    const float* __restrict__ Wv, const float* __restrict__ bv,
    float* __restrict__ Qo, float* __restrict__ Ko, float* __restrict__ Vo)
{
    const float* W = Wq; const float* bias = bq; float* out = Qo;
    if (blockIdx.z == 1) { W = Wk; bias = bk; out = Ko; }
    else if (blockIdx.z == 2) { W = Wv; bias = bv; out = Vo; }
    gemm_body(x, W, bias, out, 1);
}

__global__ __launch_bounds__(256) void oproj_kernel(
    const float* __restrict__ A, const float* __restrict__ W,
    const float* __restrict__ bias, float* __restrict__ out)
{
    gemm_body(A, W, bias, out, 0);
}

// ---------------------------------------------------------------------------
// K2: S_pos[bh][q][k] — per CTA: one q, 128-k chunk, M=32 bh, K=64.
// 4 warps, warp tile 16x64. pos_k staged once in smem (32x bh reuse).
// ---------------------------------------------------------------------------
__global__ __launch_bounds__(128) void pos_tf32(const float* __restrict__ pos_k)
{
    __shared__ float As[32 * 72];
    __shared__ float Bs[128 * 72];
    const int tid  = threadIdx.x;
    const int lane = tid & 31;
    const int g    = lane >> 2, tig = lane & 3;
    const int warp = tid >> 5;
    const int wm   = warp >> 1, wn = warp & 1;
    const int q    = blockIdx.y;
    const int kc   = blockIdx.x * 128;

#pragma unroll
    for (int i = 0; i < 4; i++) {
        int j = tid + i * 128;
        int bhh = j >> 4, d4 = (j & 15) << 2;
        float4 v = *(const float4*)(g_Q + (((size_t)bhh * 1024 + q) << 6) + d4);
        float* d = &As[bhh * 72 + d4];
        d[0] = cvt_tf32f(v.x); d[1] = cvt_tf32f(v.y);
        d[2] = cvt_tf32f(v.z); d[3] = cvt_tf32f(v.w);
    }
#pragma unroll
    for (int i = 0; i < 16; i++) {
        int j = tid + i * 128;
        int kk = j >> 4, d4 = (j & 15) << 2;
        float4 v = *(const float4*)(pos_k + (((size_t)q * 1024 + kc + kk) << 6) + d4);
        float* d = &Bs[kk * 72 + d4];
        d[0] = cvt_tf32f(v.x); d[1] = cvt_tf32f(v.y);
        d[2] = cvt_tf32f(v.z); d[3] = cvt_tf32f(v.w);
    }
    __syncthreads();

    float C[8][4];
#pragma unroll
    for (int nb = 0; nb < 8; nb++)
#pragma unroll
        for (int i = 0; i < 4; i++) C[nb][i] = 0.f;

#pragma unroll
    for (int kk = 0; kk < 8; kk++) {
        unsigned a[4];
        int r = wm * 16 + g;
        float2 t0 = *(float2*)&As[r * 72 + kk * 8 + 2 * tig];
        float2 t1 = *(float2*)&As[(r + 8) * 72 + kk * 8 + 2 * tig];
        a[0] = __float_as_uint(t0.x); a[2] = __float_as_uint(t0.y);
        a[1] = __float_as_uint(t1.x); a[3] = __float_as_uint(t1.y);
#pragma unroll
        for (int nb = 0; nb < 8; nb++) {
            float2 tb = *(float2*)&Bs[(wn * 64 + nb * 8 + g) * 72 + kk * 8 + 2 * tig];
            mma8(C[nb], a, __float_as_uint(tb.x), __float_as_uint(tb.y));
        }
    }

#pragma unroll
    for (int nb = 0; nb < 8; nb++) {
        int k   = kc + wn * 64 + nb * 8 + 2 * tig;
        int bh0 = wm * 16 + g;
        *(float2*)(g_Spos + ((size_t)bh0 * 1024 + q) * 1024 + k) =
            make_float2(C[nb][0], C[nb][1]);
        *(float2*)(g_Spos + ((size_t)(bh0 + 8) * 1024 + q) * 1024 + k) =
            make_float2(C[nb][2], C[nb][3]);
    }
}

// ---------------------------------------------------------------------------
// K3: flash attention, CTA = (bh, 64-q tile), 4 warps (warp = 16 q rows).
// Q in A-fragments (registers) for the whole CTA; P reused from C-frags.
// ---------------------------------------------------------------------------
__global__ __launch_bounds__(128) void attn_tf32()
{
    __shared__ float Ks[64 * 72];   // [k][d]
    __shared__ float Vt[64 * 72];   // [d][k]
    const int tid  = threadIdx.x;
    const int lane = tid & 31;
    const int g    = lane >> 2, tig = lane & 3;
    const int w    = tid >> 5;
    const int bh   = blockIdx.y, qt = blockIdx.x;
    const int b_   = bh >> 3, h = bh & 7;
    const int qrow = qt * 64 + w * 16;

    unsigned Qa[8][4];
    {
        const float* qb = g_Q + ((size_t)bh * 1024 + qrow) * 64;
#pragma unroll
        for (int kk = 0; kk < 8; kk++) {
            float2 t0 = *(const float2*)(qb + g * 64 + kk * 8 + 2 * tig);
            float2 t1 = *(const float2*)(qb + (g + 8) * 64 + kk * 8 + 2 * tig);
            Qa[kk][0] = cvt_tf32(t0.x); Qa[kk][2] = cvt_tf32(t0.y);
            Qa[kk][1] = cvt_tf32(t1.x); Qa[kk][3] = cvt_tf32(t1.y);
        }
    }

    float O[8][4];
#pragma unroll
    for (int nb = 0; nb < 8; nb++)
#pragma unroll
        for (int i = 0; i < 4; i++) O[nb][i] = 0.f;
    float m_a = -1e30f, m_b = -1e30f, l_a = 0.f, l_b = 0.f;

    for (int kt = 0; kt < 16; kt++) {
        const float* kbase = g_K + ((size_t)bh * 1024 + kt * 64) * 64;
        const float* vbase = g_V + ((size_t)bh * 1024 + kt * 64) * 64;
#pragma unroll
        for (int i = 0; i < 8; i++) {
            int j = tid + i * 128;
            int k = j >> 4, d4 = (j & 15) << 2;
            float4 v = *(const float4*)(kbase + (size_t)k * 64 + d4);
            float* d = &Ks[k * 72 + d4];
            d[0] = cvt_tf32f(v.x); d[1] = cvt_tf32f(v.y);
            d[2] = cvt_tf32f(v.z); d[3] = cvt_tf32f(v.w);
        }
#pragma unroll
        for (int i = 0; i < 8; i++) {
            int j = tid + i * 128;
            int k = j & 63, d4 = (j >> 6) << 2;
            float4 v = *(const float4*)(vbase + (size_t)k * 64 + d4);
            Vt[(d4 + 0) * 72 + k] = cvt_tf32f(v.x);
            Vt[(d4 + 1) * 72 + k] = cvt_tf32f(v.y);
            Vt[(d4 + 2) * 72 + k] = cvt_tf32f(v.z);
            Vt[(d4 + 3) * 72 + k] = cvt_tf32f(v.w);
        }
        __syncthreads();

        float S[8][4];
#pragma unroll
        for (int nb = 0; nb < 8; nb++)
#pragma unroll
            for (int i = 0; i < 4; i++) S[nb][i] = 0.f;

#pragma unroll
        for (int kk = 0; kk < 8; kk++)
#pragma unroll
            for (int nb = 0; nb < 8; nb++) {
                float2 tb = *(float2*)&Ks[(nb * 8 + g) * 72 + kk * 8 + 2 * tig];
                mma8(S[nb], Qa[kk], __float_as_uint(tb.x), __float_as_uint(tb.y));
            }

        const float* sp0 = g_Spos + ((size_t)bh * 1024 + qrow + g) * 1024 + kt * 64;
        const float* sp1 = sp0 + 8 * 1024;
        float ra = -1e30f, rb = -1e30f;
#pragma unroll
        for (int nb = 0; nb < 8; nb++) {
            float2 sa = *(const float2*)(sp0 + nb * 8 + 2 * tig);
            float2 sb = *(const float2*)(sp1 + nb * 8 + 2 * tig);
            S[nb][0] = (S[nb][0] + sa.x) * 0.125f;
            S[nb][1] = (S[nb][1] + sa.y) * 0.125f;
            S[nb][2] = (S[nb][2] + sb.x) * 0.125f;
            S[nb][3] = (S[nb][3] + sb.y) * 0.125f;
            ra = fmaxf(ra, fmaxf(S[nb][0], S[nb][1]));
            rb = fmaxf(rb, fmaxf(S[nb][2], S[nb][3]));
        }
        ra = fmaxf(ra, __shfl_xor_sync(0xffffffffu, ra, 1));
        ra = fmaxf(ra, __shfl_xor_sync(0xffffffffu, ra, 2));
        rb = fmaxf(rb, __shfl_xor_sync(0xffffffffu, rb, 1));
        rb = fmaxf(rb, __shfl_xor_sync(0xffffffffu, rb, 2));
        float mna = fmaxf(m_a, ra), mnb = fmaxf(m_b, rb);
        float ca = __expf(m_a - mna), cb = __expf(m_b - mnb);
        float sum_a = 0.f, sum_b = 0.f;
#pragma unroll
        for (int nb = 0; nb < 8; nb++) {
            S[nb][0] = __expf(S[nb][0] - mna);
            S[nb][1] = __expf(S[nb][1] - mna);
            S[nb][2] = __expf(S[nb][2] - mnb);
            S[nb][3] = __expf(S[nb][3] - mnb);
            sum_a += S[nb][0] + S[nb][1];
            sum_b += S[nb][2] + S[nb][3];
        }
        sum_a += __shfl_xor_sync(0xffffffffu, sum_a, 1);
        sum_a += __shfl_xor_sync(0xffffffffu, sum_a, 2);
        sum_b += __shfl_xor_sync(0xffffffffu, sum_b, 1);
        sum_b += __shfl_xor_sync(0xffffffffu, sum_b, 2);
        l_a = l_a * ca + sum_a;  l_b = l_b * cb + sum_b;
        m_a = mna;  m_b = mnb;
#pragma unroll
        for (int nb = 0; nb < 8; nb++) {
            O[nb][0] *= ca; O[nb][1] *= ca;
            O[nb][2] *= cb; O[nb][3] *= cb;
        }
        // P.V: P A-frags come straight from S C-frags (pi layout match)
#pragma unroll
        for (int kb = 0; kb < 8; kb++) {
            unsigned pa[4] = { cvt_tf32(S[kb][0]), cvt_tf32(S[kb][2]),
                               cvt_tf32(S[kb][1]), cvt_tf32(S[kb][3]) };
#pragma unroll
            for (int nb = 0; nb < 8; nb++) {
                float2 tb = *(float2*)&Vt[(nb * 8 + g) * 72 + kb * 8 + 2 * tig];
                mma8(O[nb], pa, __float_as_uint(tb.x), __float_as_uint(tb.y));
            }
        }
        __syncthreads();
    }

    float ia = 1.f / l_a, ib = 1.f / l_b;
    int t0 = qrow + g, t1 = t0 + 8;
#pragma unroll
    for (int nb = 0; nb < 8; nb++) {
        int d = h * 64 + nb * 8 + 2 * tig;
        *(float2*)(g_O + (size_t)(b_ * 1024 + t0) * 512 + d) =
            make_float2(O[nb][0] * ia, O[nb][1] * ia);
        *(float2*)(g_O + (size_t)(b_ * 1024 + t1) * 512 + d) =
            make_float2(O[nb][2] * ib, O[nb][3] * ib);
    }
}

// ---------------------------------------------------------------------------
extern "C" void kernel_launch(void* const* d_in, const int* in_sizes, int n_in,
                              void* d_out, int out_size)
{
    (void)in_sizes; (void)n_in; (void)out_size;
    const float* x    = (const float*)d_in[0];
    const float* posk = (const float*)d_in[1];
    const float* Wq = (const float*)d_in[3];
    const float* bq = (const float*)d_in[4];
    const float* Wk = (const float*)d_in[5];
    const float* bk = (const float*)d_in[6];
    const float* Wv = (const float*)d_in[7];
    const float* bv = (const float*)d_in[8];
    const float* Wo = (const float*)d_in[9];
    const float* bo = (const float*)d_in[10];
    float* out = (float*)d_out;

    float *qp, *kp, *vp, *op;
    cudaGetSymbolAddress((void**)&qp, g_Q);
    cudaGetSymbolAddress((void**)&kp, g_K);
    cudaGetSymbolAddress((void**)&vp, g_V);
    cudaGetSymbolAddress((void**)&op, g_O);

    qkv_kernel<<<dim3(4, 32, 3), 256>>>(x, Wq, bq, Wk, bk, Wv, bv, qp, kp, vp);
    pos_tf32<<<dim3(8, 1024), 128>>>(posk);
    attn_tf32<<<dim3(16, 32), 128>>>();
    oproj_kernel<<<dim3(4, 32), 256>>>(op, Wo, bo, out);
}

// round 5
// speedup vs baseline: 2.7423x; 1.3326x over previous
#include <cuda_runtime.h>
#include <cstdint>

// ---------------------------------------------------------------------------
// MultiHeadSelfAttention + relative position — legacy mma.sync tf32,
// cp.async-pipelined (tcgen05 unavailable: harness ptxas targets sm_103).
// B=4, T=1024, H=8, D=64, N_UNITS=512.
//   K0: transpose 4 weight matrices once (Wt[n][k])
//   K1: QKV projection, double-buffered cp.async
//   K2: S_pos[bh][q][k], per-CTA loop over 8 q, double-buffered pos_k stream
//   K3: flash attention, 128-q tiles, 3-stage cp.async K/V ring
//   K4: output projection
// ---------------------------------------------------------------------------

#define NBH 32
#define TSEQ 1024
#define DH 64

__device__ __align__(16) float g_Q[NBH * TSEQ * DH];
__device__ __align__(16) float g_K[NBH * TSEQ * DH];
__device__ __align__(16) float g_V[NBH * TSEQ * DH];
__device__ __align__(16) float g_O[4096 * 512];
__device__ __align__(16) float g_Spos[(size_t)NBH * TSEQ * TSEQ];  // [bh][q][k]
__device__ __align__(16) float g_Wt[4 * 512 * 512];                // W^T x4

// ---------------- helpers ---------------------------------------------------
__device__ __forceinline__ uint32_t smem_u32(const void* p) {
    uint32_t a;
    asm("{ .reg .u64 t; cvta.to.shared.u64 t, %1; cvt.u32.u64 %0, t; }"
        : "=r"(a) : "l"(p));
    return a;
}
__device__ __forceinline__ void cp_async16(uint32_t dst, const void* src) {
    asm volatile("cp.async.cg.shared.global [%0], [%1], 16;"
                 :: "r"(dst), "l"(src));
}
__device__ __forceinline__ void cp_commit() {
    asm volatile("cp.async.commit_group;");
}
template <int N> __device__ __forceinline__ void cp_wait() {
    asm volatile("cp.async.wait_group %0;" :: "n"(N));
}
__device__ __forceinline__ unsigned cvt_tf32(float x) {
    unsigned u; asm("cvt.rna.tf32.f32 %0, %1;" : "=r"(u) : "f"(x)); return u;
}
__device__ __forceinline__ void mma8(float* c, const unsigned* a,
                                     unsigned b0, unsigned b1) {
    asm volatile(
        "mma.sync.aligned.m16n8k8.row.col.f32.tf32.tf32.f32 "
        "{%0,%1,%2,%3}, {%4,%5,%6,%7}, {%8,%9}, {%0,%1,%2,%3};\n"
        : "+f"(c[0]), "+f"(c[1]), "+f"(c[2]), "+f"(c[3])
        : "r"(a[0]), "r"(a[1]), "r"(a[2]), "r"(a[3]), "r"(b0), "r"(b1));
}

// ---------------------------------------------------------------------------
// K0: 512x512 transpose x4 weights. grid (16,16,4), block (32,8).
// ---------------------------------------------------------------------------
__global__ __launch_bounds__(256) void transpose512(
    const float* __restrict__ W0, const float* __restrict__ W1,
    const float* __restrict__ W2, const float* __restrict__ W3,
    float* __restrict__ Wt)
{
    __shared__ float t[32][33];
    const float* W = W0;
    if (blockIdx.z == 1) W = W1;
    else if (blockIdx.z == 2) W = W2;
    else if (blockIdx.z == 3) W = W3;
    float* dst = Wt + (size_t)blockIdx.z * 512 * 512;
    int tx = threadIdx.x, ty = threadIdx.y;
    int x = blockIdx.x * 32 + tx, y = blockIdx.y * 32 + ty;
#pragma unroll
    for (int dy = 0; dy < 32; dy += 8)
        t[ty + dy][tx] = W[(size_t)(y + dy) * 512 + x];
    __syncthreads();
    int x2 = blockIdx.y * 32 + tx, y2 = blockIdx.x * 32 + ty;
#pragma unroll
    for (int dy = 0; dy < 32; dy += 8)
        dst[(size_t)(y2 + dy) * 512 + x2] = t[tx][ty + dy];
}

// ---------------------------------------------------------------------------
// Projection GEMM: C[4096x512] = A @ Wt^T + bias. CTA 128x128, BK=32,
// 8 warps (warp 32x64), double-buffered cp.async. dyn smem 81920 B.
// ---------------------------------------------------------------------------
#define PROJ_SMEM 81920

__device__ __forceinline__ void proj_body(
    const float* __restrict__ A, const float* __restrict__ Wt,
    const float* __restrict__ bias, float* __restrict__ out, int permute)
{
    extern __shared__ float sm[];
    float* As = sm;               // [2][128*40]
    float* Bs = sm + 2 * 5120;    // [2][128*40]
    const uint32_t asu = smem_u32(As), bsu = smem_u32(Bs);
    const int tid = threadIdx.x;
    const int lane = tid & 31, g = lane >> 2, tig = lane & 3;
    const int warp = tid >> 5, wm = warp >> 1, wn = warp & 1;
    const int mbase = blockIdx.y * 128, nbase = blockIdx.x * 128;

    float C[2][8][4];
#pragma unroll
    for (int mb = 0; mb < 2; mb++)
#pragma unroll
        for (int nb = 0; nb < 8; nb++)
#pragma unroll
            for (int i = 0; i < 4; i++) C[mb][nb][i] = 0.f;

    auto stage = [&](int buf, int k0) {
        uint32_t ab = asu + buf * 20480, bb = bsu + buf * 20480;
#pragma unroll
        for (int i = 0; i < 4; i++) {
            int c = tid + i * 256;
            int m = c >> 3, k4 = c & 7;
            cp_async16(ab + m * 160 + k4 * 16,
                       A + (size_t)(mbase + m) * 512 + k0 + k4 * 4);
            cp_async16(bb + m * 160 + k4 * 16,
                       Wt + (size_t)(nbase + m) * 512 + k0 + k4 * 4);
        }
        cp_commit();
    };
    stage(0, 0);
    stage(1, 32);

    for (int s = 0; s < 16; s++) {
        int b = s & 1;
        if (s == 15) cp_wait<0>(); else cp_wait<1>();
        __syncthreads();
        const float* as = As + b * 5120;
        const float* bs = Bs + b * 5120;
#pragma unroll
        for (int kk = 0; kk < 4; kk++) {
            unsigned a[2][4];
#pragma unroll
            for (int mb = 0; mb < 2; mb++) {
                int r = wm * 32 + mb * 16 + g;
                float2 t0 = *(const float2*)&as[r * 40 + kk * 8 + 2 * tig];
                float2 t1 = *(const float2*)&as[(r + 8) * 40 + kk * 8 + 2 * tig];
                a[mb][0] = __float_as_uint(t0.x);
                a[mb][2] = __float_as_uint(t0.y);
                a[mb][1] = __float_as_uint(t1.x);
                a[mb][3] = __float_as_uint(t1.y);
            }
#pragma unroll
            for (int nb = 0; nb < 8; nb++) {
                float2 tb = *(const float2*)&bs[(wn * 64 + nb * 8 + g) * 40 + kk * 8 + 2 * tig];
                unsigned b0 = __float_as_uint(tb.x), b1 = __float_as_uint(tb.y);
                mma8(C[0][nb], a[0], b0, b1);
                mma8(C[1][nb], a[1], b0, b1);
            }
        }
        __syncthreads();
        if (s + 2 < 16) stage(b, (s + 2) * 32);
    }

#pragma unroll
    for (int nb = 0; nb < 8; nb++) {
        int ncol = wn * 64 + nb * 8 + 2 * tig;
        float2 bb = *(const float2*)(bias + nbase + ncol);
#pragma unroll
        for (int mb = 0; mb < 2; mb++) {
            int r0 = mbase + wm * 32 + mb * 16 + g;
            int r1 = r0 + 8;
            float2 v0 = make_float2(C[mb][nb][0] + bb.x, C[mb][nb][1] + bb.y);
            float2 v1 = make_float2(C[mb][nb][2] + bb.x, C[mb][nb][3] + bb.y);
            if (permute) {
                int h = (nbase >> 6) + wn;
                int d = nb * 8 + 2 * tig;
                *(float2*)(out + (((size_t)((r0 >> 10) * 8 + h) * 1024 + (r0 & 1023)) << 6) + d) = v0;
                *(float2*)(out + (((size_t)((r1 >> 10) * 8 + h) * 1024 + (r1 & 1023)) << 6) + d) = v1;
            } else {
                *(float2*)(out + (size_t)r0 * 512 + nbase + ncol) = v0;
                *(float2*)(out + (size_t)r1 * 512 + nbase + ncol) = v1;
            }
        }
    }
}

__global__ __launch_bounds__(256) void qkv_kernel(
    const float* __restrict__ x, const float* __restrict__ Wt,
    const float* __restrict__ bq, const float* __restrict__ bk,
    const float* __restrict__ bv,
    float* __restrict__ Qo, float* __restrict__ Ko, float* __restrict__ Vo)
{
    const float* wt = Wt; const float* bias = bq; float* out = Qo;
    if (blockIdx.z == 1) { wt = Wt + 262144;      bias = bk; out = Ko; }
    else if (blockIdx.z == 2) { wt = Wt + 524288; bias = bv; out = Vo; }
    proj_body(x, wt, bias, out, 1);
}
__global__ __launch_bounds__(256) void oproj_kernel(
    const float* __restrict__ A, const float* __restrict__ Wt,
    const float* __restrict__ bias, float* __restrict__ out)
{
    proj_body(A, Wt, bias, out, 0);
}

// ---------------------------------------------------------------------------
// K2: S_pos. CTA = (k-chunk 256, q-group of 8). 256 thr, 8 warps (16bh x 64k).
// Double-buffered cp.async over the q loop. dyn smem 165888 B.
// ---------------------------------------------------------------------------
#define POS_SMEM 165888

__global__ __launch_bounds__(256) void pos_kernel(const float* __restrict__ pos_k)
{
    extern __shared__ float sm[];
    float* As = sm;               // [2][32*72]
    float* Bs = sm + 2 * 2304;    // [2][256*72]
    const uint32_t asu = smem_u32(As), bsu = smem_u32(Bs);
    const int tid = threadIdx.x;
    const int lane = tid & 31, g = lane >> 2, tig = lane & 3;
    const int w = tid >> 5, wm = w >> 2, wn = w & 3;
    const int q0 = blockIdx.y * 8, kc = blockIdx.x * 256;

    auto stage = [&](int buf, int qi) {
        int q = q0 + qi;
#pragma unroll
        for (int i = 0; i < 2; i++) {
            int c = tid + i * 256;
            int r = c >> 4, k4 = c & 15;
            cp_async16(asu + buf * 9216 + r * 288 + k4 * 16,
                       g_Q + ((size_t)r * 1024 + q) * 64 + k4 * 4);
        }
#pragma unroll
        for (int i = 0; i < 16; i++) {
            int c = tid + i * 256;
            int r = c >> 4, k4 = c & 15;
            cp_async16(bsu + buf * 73728 + r * 288 + k4 * 16,
                       pos_k + ((size_t)q * 1024 + kc + r) * 64 + k4 * 4);
        }
        cp_commit();
    };
    stage(0, 0);
    stage(1, 1);

    for (int i = 0; i < 8; i++) {
        int b = i & 1;
        if (i == 7) cp_wait<0>(); else cp_wait<1>();
        __syncthreads();
        const float* as = As + b * 2304;
        const float* bs = Bs + b * 18432;

        float C[8][4];
#pragma unroll
        for (int nb = 0; nb < 8; nb++)
#pragma unroll
            for (int j = 0; j < 4; j++) C[nb][j] = 0.f;

#pragma unroll
        for (int kk = 0; kk < 8; kk++) {
            unsigned a[4];
            int r = wm * 16 + g;
            float2 t0 = *(const float2*)&as[r * 72 + kk * 8 + 2 * tig];
            float2 t1 = *(const float2*)&as[(r + 8) * 72 + kk * 8 + 2 * tig];
            a[0] = __float_as_uint(t0.x); a[2] = __float_as_uint(t0.y);
            a[1] = __float_as_uint(t1.x); a[3] = __float_as_uint(t1.y);
#pragma unroll
            for (int nb = 0; nb < 8; nb++) {
                float2 tb = *(const float2*)&bs[(wn * 64 + nb * 8 + g) * 72 + kk * 8 + 2 * tig];
                mma8(C[nb], a, __float_as_uint(tb.x), __float_as_uint(tb.y));
            }
        }

        int q = q0 + i;
#pragma unroll
        for (int nb = 0; nb < 8; nb++) {
            int k = kc + wn * 64 + nb * 8 + 2 * tig;
            int bh0 = wm * 16 + g;
            *(float2*)(g_Spos + ((size_t)bh0 * 1024 + q) * 1024 + k) =
                make_float2(C[nb][0], C[nb][1]);
            *(float2*)(g_Spos + ((size_t)(bh0 + 8) * 1024 + q) * 1024 + k) =
                make_float2(C[nb][2], C[nb][3]);
        }
        __syncthreads();
        if (i + 2 < 8) stage(b, i + 2);
    }
}

// ---------------------------------------------------------------------------
// K3: flash attention. CTA = (bh, 128-q tile), 8 warps (16 q rows each).
// 3-stage cp.async K/V ring (one sync/iter), V consumed untransposed.
// dyn smem 110592 B.
// ---------------------------------------------------------------------------
#define ATTN_SMEM 110592

__global__ __launch_bounds__(256) void attn_kernel()
{
    extern __shared__ float sm[];
    float* Ks = sm;               // [3][64*72]
    float* Vs = sm + 3 * 4608;    // [3][64*72]
    const uint32_t ksu = smem_u32(Ks), vsu = smem_u32(Vs);
    const int tid = threadIdx.x;
    const int lane = tid & 31, g = lane >> 2, tig = lane & 3;
    const int w = tid >> 5;
    const int bh = blockIdx.y, qt = blockIdx.x;
    const int b_ = bh >> 3, h = bh & 7;
    const int qrow = qt * 128 + w * 16;

    unsigned Qa[8][4];
    {
        const float* qb = g_Q + ((size_t)bh * 1024 + qrow) * 64;
#pragma unroll
        for (int kk = 0; kk < 8; kk++) {
            float2 t0 = *(const float2*)(qb + g * 64 + kk * 8 + 2 * tig);
            float2 t1 = *(const float2*)(qb + (g + 8) * 64 + kk * 8 + 2 * tig);
            Qa[kk][0] = cvt_tf32(t0.x); Qa[kk][2] = cvt_tf32(t0.y);
            Qa[kk][1] = cvt_tf32(t1.x); Qa[kk][3] = cvt_tf32(t1.y);
        }
    }

    auto stage = [&](int buf, int kt) {
        const size_t baseK = ((size_t)bh * 1024 + kt * 64) * 64;
#pragma unroll
        for (int i = 0; i < 4; i++) {
            int c = tid + i * 256;
            int r = c >> 4, k4 = c & 15;
            cp_async16(ksu + buf * 18432 + r * 288 + k4 * 16,
                       g_K + baseK + r * 64 + k4 * 4);
            cp_async16(vsu + buf * 18432 + r * 288 + k4 * 16,
                       g_V + baseK + r * 64 + k4 * 4);
        }
        cp_commit();
    };
    stage(0, 0);
    stage(1, 1);

    float O[8][4];
#pragma unroll
    for (int nb = 0; nb < 8; nb++)
#pragma unroll
        for (int i = 0; i < 4; i++) O[nb][i] = 0.f;
    float m_a = -1e30f, m_b = -1e30f, l_a = 0.f, l_b = 0.f;

    for (int kt = 0; kt < 16; kt++) {
        int b = kt % 3;
        if (kt == 15) cp_wait<0>(); else cp_wait<1>();
        __syncthreads();
        if (kt + 2 < 16) stage((kt + 2) % 3, kt + 2);

        // prefetch pos scores for this tile
        const float* sp0 = g_Spos + ((size_t)bh * 1024 + qrow + g) * 1024 + kt * 64;
        const float* sp1 = sp0 + 8 * 1024;
        float2 spa[8], spb[8];
#pragma unroll
        for (int nb = 0; nb < 8; nb++) {
            spa[nb] = *(const float2*)(sp0 + nb * 8 + 2 * tig);
            spb[nb] = *(const float2*)(sp1 + nb * 8 + 2 * tig);
        }

        const float* ks = Ks + b * 4608;
        const float* vs = Vs + b * 4608;

        float S[8][4];
#pragma unroll
        for (int nb = 0; nb < 8; nb++)
#pragma unroll
            for (int i = 0; i < 4; i++) S[nb][i] = 0.f;
#pragma unroll
        for (int kk = 0; kk < 8; kk++)
#pragma unroll
            for (int nb = 0; nb < 8; nb++) {
                float2 tb = *(const float2*)&ks[(nb * 8 + g) * 72 + kk * 8 + 2 * tig];
                mma8(S[nb], Qa[kk], __float_as_uint(tb.x), __float_as_uint(tb.y));
            }

        float ra = -1e30f, rb = -1e30f;
#pragma unroll
        for (int nb = 0; nb < 8; nb++) {
            S[nb][0] = (S[nb][0] + spa[nb].x) * 0.125f;
            S[nb][1] = (S[nb][1] + spa[nb].y) * 0.125f;
            S[nb][2] = (S[nb][2] + spb[nb].x) * 0.125f;
            S[nb][3] = (S[nb][3] + spb[nb].y) * 0.125f;
            ra = fmaxf(ra, fmaxf(S[nb][0], S[nb][1]));
            rb = fmaxf(rb, fmaxf(S[nb][2], S[nb][3]));
        }
        ra = fmaxf(ra, __shfl_xor_sync(0xffffffffu, ra, 1));
        ra = fmaxf(ra, __shfl_xor_sync(0xffffffffu, ra, 2));
        rb = fmaxf(rb, __shfl_xor_sync(0xffffffffu, rb, 1));
        rb = fmaxf(rb, __shfl_xor_sync(0xffffffffu, rb, 2));
        float mna = fmaxf(m_a, ra), mnb = fmaxf(m_b, rb);
        float ca = __expf(m_a - mna), cb = __expf(m_b - mnb);
        float sum_a = 0.f, sum_b = 0.f;
#pragma unroll
        for (int nb = 0; nb < 8; nb++) {
            S[nb][0] = __expf(S[nb][0] - mna);
            S[nb][1] = __expf(S[nb][1] - mna);
            S[nb][2] = __expf(S[nb][2] - mnb);
            S[nb][3] = __expf(S[nb][3] - mnb);
            sum_a += S[nb][0] + S[nb][1];
            sum_b += S[nb][2] + S[nb][3];
        }
        sum_a += __shfl_xor_sync(0xffffffffu, sum_a, 1);
        sum_a += __shfl_xor_sync(0xffffffffu, sum_a, 2);
        sum_b += __shfl_xor_sync(0xffffffffu, sum_b, 1);
        sum_b += __shfl_xor_sync(0xffffffffu, sum_b, 2);
        l_a = l_a * ca + sum_a;  l_b = l_b * cb + sum_b;
        m_a = mna;  m_b = mnb;
#pragma unroll
        for (int nb = 0; nb < 8; nb++) {
            O[nb][0] *= ca; O[nb][1] *= ca;
            O[nb][2] *= cb; O[nb][3] *= cb;
        }
        // P.V: P A-frags from S C-frags; V read untransposed from Vs[k][d]
#pragma unroll
        for (int kb = 0; kb < 8; kb++) {
            unsigned pa[4] = { cvt_tf32(S[kb][0]), cvt_tf32(S[kb][2]),
                               cvt_tf32(S[kb][1]), cvt_tf32(S[kb][3]) };
#pragma unroll
            for (int nb = 0; nb < 8; nb++) {
                float b0f = vs[(kb * 8 + 2 * tig) * 72 + nb * 8 + g];
                float b1f = vs[(kb * 8 + 2 * tig + 1) * 72 + nb * 8 + g];
                mma8(O[nb], pa, __float_as_uint(b0f), __float_as_uint(b1f));
            }
        }
    }

    float ia = 1.f / l_a, ib = 1.f / l_b;
    int t0 = qrow + g, t1 = t0 + 8;
#pragma unroll
    for (int nb = 0; nb < 8; nb++) {
        int d = h * 64 + nb * 8 + 2 * tig;
        *(float2*)(g_O + (size_t)(b_ * 1024 + t0) * 512 + d) =
            make_float2(O[nb][0] * ia, O[nb][1] * ia);
        *(float2*)(g_O + (size_t)(b_ * 1024 + t1) * 512 + d) =
            make_float2(O[nb][2] * ib, O[nb][3] * ib);
    }
}

// ---------------------------------------------------------------------------
extern "C" void kernel_launch(void* const* d_in, const int* in_sizes, int n_in,
                              void* d_out, int out_size)
{
    (void)in_sizes; (void)n_in; (void)out_size;
    const float* x    = (const float*)d_in[0];
    const float* posk = (const float*)d_in[1];
    const float* Wq = (const float*)d_in[3];
    const float* bq = (const float*)d_in[4];
    const float* Wk = (const float*)d_in[5];
    const float* bk = (const float*)d_in[6];
    const float* Wv = (const float*)d_in[7];
    const float* bv = (const float*)d_in[8];
    const float* Wo = (const float*)d_in[9];
    const float* bo = (const float*)d_in[10];
    float* out = (float*)d_out;

    float *qp, *kp, *vp, *op, *wtp;
    cudaGetSymbolAddress((void**)&qp, g_Q);
    cudaGetSymbolAddress((void**)&kp, g_K);
    cudaGetSymbolAddress((void**)&vp, g_V);
    cudaGetSymbolAddress((void**)&op, g_O);
    cudaGetSymbolAddress((void**)&wtp, g_Wt);

    cudaFuncSetAttribute(qkv_kernel,
                         cudaFuncAttributeMaxDynamicSharedMemorySize, PROJ_SMEM);
    cudaFuncSetAttribute(oproj_kernel,
                         cudaFuncAttributeMaxDynamicSharedMemorySize, PROJ_SMEM);
    cudaFuncSetAttribute(pos_kernel,
                         cudaFuncAttributeMaxDynamicSharedMemorySize, POS_SMEM);
    cudaFuncSetAttribute(attn_kernel,
                         cudaFuncAttributeMaxDynamicSharedMemorySize, ATTN_SMEM);

    transpose512<<<dim3(16, 16, 4), dim3(32, 8)>>>(Wq, Wk, Wv, Wo, wtp);
    qkv_kernel<<<dim3(4, 32, 3), 256, PROJ_SMEM>>>(x, wtp, bq, bk, bv, qp, kp, vp);
    pos_kernel<<<dim3(4, 128), 256, POS_SMEM>>>(posk);
    attn_kernel<<<dim3(8, 32), 256, ATTN_SMEM>>>();
    oproj_kernel<<<dim3(4, 32), 256, PROJ_SMEM>>>(op, wtp + 3 * 262144, bo, out);
}

// round 6
// speedup vs baseline: 3.3420x; 1.2187x over previous
#include <cuda_runtime.h>
#include <cstdint>

// ---------------------------------------------------------------------------
// MultiHeadSelfAttention + relative position — legacy mma.sync tf32.
// All mma inputs pre-rounded to exact tf32 at production time (rounding is
// then free inside the mma). 2 CTAs/SM everywhere. V stored transposed.
//   K0: prep — transpose+round 4 weights, round x
//   K1: QKV projection (Q,K: [bh][t][d]; V: [bh][d][t]), rounded epilogues
//   K2: S_pos[bh][q][k] (pos_k streamed once, cvt.rna in-register)
//   K3: flash attention, 128-q tiles, 2-stage cp.async ring, float2 PV frags
//   K4: output projection (full-precision output)
// ---------------------------------------------------------------------------

#define NBH 32
#define TSEQ 1024
#define DH 64

__device__ __align__(16) float g_Q[NBH * TSEQ * DH];
__device__ __align__(16) float g_K[NBH * TSEQ * DH];
__device__ __align__(16) float g_V[NBH * TSEQ * DH];     // [bh][d][t] !
__device__ __align__(16) float g_O[4096 * 512];
__device__ __align__(16) float g_Spos[(size_t)NBH * TSEQ * TSEQ];  // [bh][q][k]
__device__ __align__(16) float g_Wt[4 * 512 * 512];      // W^T, tf32-rounded
__device__ __align__(16) float g_xt[4096 * 512];         // x, tf32-rounded

// ---------------- helpers ---------------------------------------------------
__device__ __forceinline__ uint32_t smem_u32(const void* p) {
    uint32_t a;
    asm("{ .reg .u64 t; cvta.to.shared.u64 t, %1; cvt.u32.u64 %0, t; }"
        : "=r"(a) : "l"(p));
    return a;
}
__device__ __forceinline__ void cp_async16(uint32_t dst, const void* src) {
    asm volatile("cp.async.cg.shared.global [%0], [%1], 16;"
                 :: "r"(dst), "l"(src));
}
__device__ __forceinline__ void cp_commit() {
    asm volatile("cp.async.commit_group;");
}
template <int N> __device__ __forceinline__ void cp_wait() {
    asm volatile("cp.async.wait_group %0;" :: "n"(N));
}
__device__ __forceinline__ unsigned cvt_tf32(float x) {
    unsigned u; asm("cvt.rna.tf32.f32 %0, %1;" : "=r"(u) : "f"(x)); return u;
}
__device__ __forceinline__ float cvt_tf32f(float x) {
    return __uint_as_float(cvt_tf32(x));
}
__device__ __forceinline__ void mma8(float* c, const unsigned* a,
                                     unsigned b0, unsigned b1) {
    asm volatile(
        "mma.sync.aligned.m16n8k8.row.col.f32.tf32.tf32.f32 "
        "{%0,%1,%2,%3}, {%4,%5,%6,%7}, {%8,%9}, {%0,%1,%2,%3};\n"
        : "+f"(c[0]), "+f"(c[1]), "+f"(c[2]), "+f"(c[3])
        : "r"(a[0]), "r"(a[1]), "r"(a[2]), "r"(a[3]), "r"(b0), "r"(b1));
}

// ---------------------------------------------------------------------------
// K0: prep. z<4: transpose+round weight z. z==4: round x into g_xt.
// grid (16,16,5), block (32,8).
// ---------------------------------------------------------------------------
__global__ __launch_bounds__(256) void prep_kernel(
    const float* __restrict__ W0, const float* __restrict__ W1,
    const float* __restrict__ W2, const float* __restrict__ W3,
    const float* __restrict__ x)
{
    int tx = threadIdx.x, ty = threadIdx.y;
    if (blockIdx.z == 4) {
        int t = ty * 32 + tx;
        size_t base = ((size_t)blockIdx.y * 16 + blockIdx.x) * 8192;
#pragma unroll
        for (int j = 0; j < 8; j++) {
            size_t i = base + ((size_t)(t + j * 256) << 2);
            float4 v = *(const float4*)(x + i);
            *(float4*)(g_xt + i) = make_float4(cvt_tf32f(v.x), cvt_tf32f(v.y),
                                               cvt_tf32f(v.z), cvt_tf32f(v.w));
        }
        return;
    }
    __shared__ float t[32][33];
    const float* W = W0;
    if (blockIdx.z == 1) W = W1;
    else if (blockIdx.z == 2) W = W2;
    else if (blockIdx.z == 3) W = W3;
    float* dst = g_Wt + (size_t)blockIdx.z * 512 * 512;
    int x0 = blockIdx.x * 32 + tx, y0 = blockIdx.y * 32 + ty;
#pragma unroll
    for (int dy = 0; dy < 32; dy += 8)
        t[ty + dy][tx] = W[(size_t)(y0 + dy) * 512 + x0];
    __syncthreads();
    int x2 = blockIdx.y * 32 + tx, y2 = blockIdx.x * 32 + ty;
#pragma unroll
    for (int dy = 0; dy < 32; dy += 8)
        dst[(size_t)(y2 + dy) * 512 + x2] = cvt_tf32f(t[tx][ty + dy]);
}

// ---------------------------------------------------------------------------
// Projection GEMM: C[4096x512] = A @ Wt^T + bias. CTA 128x128, BK=32,
// 8 warps (warp 32x64), double-buffered cp.async. dyn smem 81920 B.
// permute: 0 = row-major full fp32 (final out); 1 = [bh][t][d] rounded (Q,K);
//          2 = [bh][d][t] rounded (V); 3 = row-major rounded (unused)
// ---------------------------------------------------------------------------
#define PROJ_SMEM 81920

__device__ __forceinline__ void proj_body(
    const float* __restrict__ A, const float* __restrict__ Wt,
    const float* __restrict__ bias, float* __restrict__ out, int permute)
{
    extern __shared__ float sm[];
    float* As = sm;               // [2][128*40]
    float* Bs = sm + 2 * 5120;    // [2][128*40]
    const uint32_t asu = smem_u32(As), bsu = smem_u32(Bs);
    const int tid = threadIdx.x;
    const int lane = tid & 31, g = lane >> 2, tig = lane & 3;
    const int warp = tid >> 5, wm = warp >> 1, wn = warp & 1;
    const int mbase = blockIdx.y * 128, nbase = blockIdx.x * 128;

    float C[2][8][4];
#pragma unroll
    for (int mb = 0; mb < 2; mb++)
#pragma unroll
        for (int nb = 0; nb < 8; nb++)
#pragma unroll
            for (int i = 0; i < 4; i++) C[mb][nb][i] = 0.f;

    auto stage = [&](int buf, int k0) {
        uint32_t ab = asu + buf * 20480, bb = bsu + buf * 20480;
#pragma unroll
        for (int i = 0; i < 4; i++) {
            int c = tid + i * 256;
            int m = c >> 3, k4 = c & 7;
            cp_async16(ab + m * 160 + k4 * 16,
                       A + (size_t)(mbase + m) * 512 + k0 + k4 * 4);
            cp_async16(bb + m * 160 + k4 * 16,
                       Wt + (size_t)(nbase + m) * 512 + k0 + k4 * 4);
        }
        cp_commit();
    };
    stage(0, 0);
    stage(1, 32);

    for (int s = 0; s < 16; s++) {
        int b = s & 1;
        if (s == 15) cp_wait<0>(); else cp_wait<1>();
        __syncthreads();
        const float* as = As + b * 5120;
        const float* bs = Bs + b * 5120;
#pragma unroll
        for (int kk = 0; kk < 4; kk++) {
            unsigned a[2][4];
#pragma unroll
            for (int mb = 0; mb < 2; mb++) {
                int r = wm * 32 + mb * 16 + g;
                float2 t0 = *(const float2*)&as[r * 40 + kk * 8 + 2 * tig];
                float2 t1 = *(const float2*)&as[(r + 8) * 40 + kk * 8 + 2 * tig];
                a[mb][0] = __float_as_uint(t0.x);
                a[mb][2] = __float_as_uint(t0.y);
                a[mb][1] = __float_as_uint(t1.x);
                a[mb][3] = __float_as_uint(t1.y);
            }
#pragma unroll
            for (int nb = 0; nb < 8; nb++) {
                float2 tb = *(const float2*)&bs[(wn * 64 + nb * 8 + g) * 40 + kk * 8 + 2 * tig];
                unsigned b0 = __float_as_uint(tb.x), b1 = __float_as_uint(tb.y);
                mma8(C[0][nb], a[0], b0, b1);
                mma8(C[1][nb], a[1], b0, b1);
            }
        }
        __syncthreads();
        if (s + 2 < 16) stage(b, (s + 2) * 32);
    }

#pragma unroll
    for (int nb = 0; nb < 8; nb++) {
        int ncol = wn * 64 + nb * 8 + 2 * tig;
        float2 bb = *(const float2*)(bias + nbase + ncol);
#pragma unroll
        for (int mb = 0; mb < 2; mb++) {
            int r0 = mbase + wm * 32 + mb * 16 + g;
            int r1 = r0 + 8;
            float2 v0 = make_float2(C[mb][nb][0] + bb.x, C[mb][nb][1] + bb.y);
            float2 v1 = make_float2(C[mb][nb][2] + bb.x, C[mb][nb][3] + bb.y);
            if (permute == 1) {
                v0 = make_float2(cvt_tf32f(v0.x), cvt_tf32f(v0.y));
                v1 = make_float2(cvt_tf32f(v1.x), cvt_tf32f(v1.y));
                int h = (nbase >> 6) + wn;
                int d = nb * 8 + 2 * tig;
                *(float2*)(out + (((size_t)((r0 >> 10) * 8 + h) * 1024 + (r0 & 1023)) << 6) + d) = v0;
                *(float2*)(out + (((size_t)((r1 >> 10) * 8 + h) * 1024 + (r1 & 1023)) << 6) + d) = v1;
            } else if (permute == 2) {
                int h = (nbase >> 6) + wn;
                int d = nb * 8 + 2 * tig;
                size_t base = ((size_t)((r0 >> 10) * 8 + h) * 64 + d) * 1024;
                int t0 = r0 & 1023, t1 = r1 & 1023;
                out[base + t0]        = cvt_tf32f(v0.x);
                out[base + 1024 + t0] = cvt_tf32f(v0.y);
                out[base + t1]        = cvt_tf32f(v1.x);
                out[base + 1024 + t1] = cvt_tf32f(v1.y);
            } else {
                *(float2*)(out + (size_t)r0 * 512 + nbase + ncol) = v0;
                *(float2*)(out + (size_t)r1 * 512 + nbase + ncol) = v1;
            }
        }
    }
}

__global__ __launch_bounds__(256, 2) void qkv_kernel(
    const float* __restrict__ x, const float* __restrict__ Wt,
    const float* __restrict__ bq, const float* __restrict__ bk,
    const float* __restrict__ bv,
    float* __restrict__ Qo, float* __restrict__ Ko, float* __restrict__ Vo)
{
    const float* wt = Wt; const float* bias = bq; float* out = Qo; int perm = 1;
    if (blockIdx.z == 1) { wt = Wt + 262144;      bias = bk; out = Ko; }
    else if (blockIdx.z == 2) { wt = Wt + 524288; bias = bv; out = Vo; perm = 2; }
    proj_body(x, wt, bias, out, perm);
}
__global__ __launch_bounds__(256, 2) void oproj_kernel(
    const float* __restrict__ A, const float* __restrict__ Wt,
    const float* __restrict__ bias, float* __restrict__ out)
{
    proj_body(A, Wt, bias, out, 0);
}

// ---------------------------------------------------------------------------
// K2: S_pos. CTA = (k-chunk 128, q-group of 8). 256 thr, 8 warps (16bh x 32k).
// Double-buffered cp.async over the q loop. dyn smem 92160 B (2 CTAs/SM).
// pos_k fragments cvt.rna in-register (kernel is memory-bound; ALU free).
// ---------------------------------------------------------------------------
#define POS_SMEM 92160

__global__ __launch_bounds__(256, 2) void pos_kernel(const float* __restrict__ pos_k)
{
    extern __shared__ float sm[];
    float* As = sm;               // [2][32*72]
    float* Bs = sm + 2 * 2304;    // [2][128*72]
    const uint32_t asu = smem_u32(As), bsu = smem_u32(Bs);
    const int tid = threadIdx.x;
    const int lane = tid & 31, g = lane >> 2, tig = lane & 3;
    const int w = tid >> 5, wm = w >> 2, wn = w & 3;
    const int q0 = blockIdx.y * 8, kc = blockIdx.x * 128;

    auto stage = [&](int buf, int qi) {
        int q = q0 + qi;
#pragma unroll
        for (int i = 0; i < 2; i++) {
            int c = tid + i * 256;
            int r = c >> 4, k4 = c & 15;
            cp_async16(asu + buf * 9216 + r * 288 + k4 * 16,
                       g_Q + ((size_t)r * 1024 + q) * 64 + k4 * 4);
        }
#pragma unroll
        for (int i = 0; i < 8; i++) {
            int c = tid + i * 256;
            int r = c >> 4, k4 = c & 15;
            cp_async16(bsu + buf * 36864 + r * 288 + k4 * 16,
                       pos_k + ((size_t)q * 1024 + kc + r) * 64 + k4 * 4);
        }
        cp_commit();
    };
    stage(0, 0);
    stage(1, 1);

    for (int i = 0; i < 8; i++) {
        int b = i & 1;
        if (i == 7) cp_wait<0>(); else cp_wait<1>();
        __syncthreads();
        const float* as = As + b * 2304;
        const float* bs = Bs + b * 9216;

        float C[4][4];
#pragma unroll
        for (int nb = 0; nb < 4; nb++)
#pragma unroll
            for (int j = 0; j < 4; j++) C[nb][j] = 0.f;

#pragma unroll
        for (int kk = 0; kk < 8; kk++) {
            unsigned a[4];
            int r = wm * 16 + g;
            float2 t0 = *(const float2*)&as[r * 72 + kk * 8 + 2 * tig];
            float2 t1 = *(const float2*)&as[(r + 8) * 72 + kk * 8 + 2 * tig];
            a[0] = __float_as_uint(t0.x); a[2] = __float_as_uint(t0.y);
            a[1] = __float_as_uint(t1.x); a[3] = __float_as_uint(t1.y);
#pragma unroll
            for (int nb = 0; nb < 4; nb++) {
                float2 tb = *(const float2*)&bs[(wn * 32 + nb * 8 + g) * 72 + kk * 8 + 2 * tig];
                mma8(C[nb], a, cvt_tf32(tb.x), cvt_tf32(tb.y));
            }
        }

        int q = q0 + i;
#pragma unroll
        for (int nb = 0; nb < 4; nb++) {
            int k = kc + wn * 32 + nb * 8 + 2 * tig;
            int bh0 = wm * 16 + g;
            *(float2*)(g_Spos + ((size_t)bh0 * 1024 + q) * 1024 + k) =
                make_float2(C[nb][0], C[nb][1]);
            *(float2*)(g_Spos + ((size_t)(bh0 + 8) * 1024 + q) * 1024 + k) =
                make_float2(C[nb][2], C[nb][3]);
        }
        __syncthreads();
        if (i + 2 < 8) stage(b, i + 2);
    }
}

// ---------------------------------------------------------------------------
// K3: flash attention. CTA = (bh, 128-q tile), 8 warps (16 q rows each).
// 2-stage cp.async ring, V staged transposed [d][k] -> float2 PV fragments.
// dyn smem 73728 B (2 CTAs/SM).
// ---------------------------------------------------------------------------
#define ATTN_SMEM 73728

__global__ __launch_bounds__(256, 2) void attn_kernel()
{
    extern __shared__ float sm[];
    float* Ks = sm;               // [2][64*72]  [k][d]
    float* Vs = sm + 2 * 4608;    // [2][64*72]  [d][k]
    const uint32_t ksu = smem_u32(Ks), vsu = smem_u32(Vs);
    const int tid = threadIdx.x;
    const int lane = tid & 31, g = lane >> 2, tig = lane & 3;
    const int w = tid >> 5;
    const int bh = blockIdx.y, qt = blockIdx.x;
    const int b_ = bh >> 3, h = bh & 7;
    const int qrow = qt * 128 + w * 16;

    unsigned Qa[8][4];
    {
        const float* qb = g_Q + ((size_t)bh * 1024 + qrow) * 64;
#pragma unroll
        for (int kk = 0; kk < 8; kk++) {
            float2 t0 = *(const float2*)(qb + g * 64 + kk * 8 + 2 * tig);
            float2 t1 = *(const float2*)(qb + (g + 8) * 64 + kk * 8 + 2 * tig);
            Qa[kk][0] = __float_as_uint(t0.x); Qa[kk][2] = __float_as_uint(t0.y);
            Qa[kk][1] = __float_as_uint(t1.x); Qa[kk][3] = __float_as_uint(t1.y);
        }
    }

    auto stage = [&](int buf, int kt) {
        const size_t baseK = ((size_t)bh * 1024 + kt * 64) * 64;
        const size_t baseV = ((size_t)bh * 64) * 1024 + kt * 64;
#pragma unroll
        for (int i = 0; i < 4; i++) {
            int c = tid + i * 256;
            int r = c >> 4, k4 = c & 15;
            cp_async16(ksu + buf * 18432 + r * 288 + k4 * 16,
                       g_K + baseK + r * 64 + k4 * 4);
            cp_async16(vsu + buf * 18432 + r * 288 + k4 * 16,
                       g_V + baseV + (size_t)r * 1024 + k4 * 4);
        }
        cp_commit();
    };
    stage(0, 0);
    stage(1, 1);

    float O[8][4];
#pragma unroll
    for (int nb = 0; nb < 8; nb++)
#pragma unroll
        for (int i = 0; i < 4; i++) O[nb][i] = 0.f;
    float m_a = -1e30f, m_b = -1e30f, l_a = 0.f, l_b = 0.f;

    for (int kt = 0; kt < 16; kt++) {
        int b = kt & 1;
        if (kt == 15) cp_wait<0>(); else cp_wait<1>();
        __syncthreads();

        // prefetch pos scores for this tile (lands during QK mma block)
        const float* sp0 = g_Spos + ((size_t)bh * 1024 + qrow + g) * 1024 + kt * 64;
        const float* sp1 = sp0 + 8 * 1024;
        float2 spa[8], spb[8];
#pragma unroll
        for (int nb = 0; nb < 8; nb++) {
            spa[nb] = *(const float2*)(sp0 + nb * 8 + 2 * tig);
            spb[nb] = *(const float2*)(sp1 + nb * 8 + 2 * tig);
        }

        const float* ks = Ks + b * 4608;
        const float* vs = Vs + b * 4608;

        float S[8][4];
#pragma unroll
        for (int nb = 0; nb < 8; nb++)
#pragma unroll
            for (int i = 0; i < 4; i++) S[nb][i] = 0.f;
#pragma unroll
        for (int kk = 0; kk < 8; kk++)
#pragma unroll
            for (int nb = 0; nb < 8; nb++) {
                float2 tb = *(const float2*)&ks[(nb * 8 + g) * 72 + kk * 8 + 2 * tig];
                mma8(S[nb], Qa[kk], __float_as_uint(tb.x), __float_as_uint(tb.y));
            }

        float ra = -1e30f, rb = -1e30f;
#pragma unroll
        for (int nb = 0; nb < 8; nb++) {
            S[nb][0] = (S[nb][0] + spa[nb].x) * 0.125f;
            S[nb][1] = (S[nb][1] + spa[nb].y) * 0.125f;
            S[nb][2] = (S[nb][2] + spb[nb].x) * 0.125f;
            S[nb][3] = (S[nb][3] + spb[nb].y) * 0.125f;
            ra = fmaxf(ra, fmaxf(S[nb][0], S[nb][1]));
            rb = fmaxf(rb, fmaxf(S[nb][2], S[nb][3]));
        }
        ra = fmaxf(ra, __shfl_xor_sync(0xffffffffu, ra, 1));
        ra = fmaxf(ra, __shfl_xor_sync(0xffffffffu, ra, 2));
        rb = fmaxf(rb, __shfl_xor_sync(0xffffffffu, rb, 1));
        rb = fmaxf(rb, __shfl_xor_sync(0xffffffffu, rb, 2));
        float mna = fmaxf(m_a, ra), mnb = fmaxf(m_b, rb);
        float ca = __expf(m_a - mna), cb = __expf(m_b - mnb);
        float sum_a = 0.f, sum_b = 0.f;
#pragma unroll
        for (int nb = 0; nb < 8; nb++) {
            S[nb][0] = __expf(S[nb][0] - mna);
            S[nb][1] = __expf(S[nb][1] - mna);
            S[nb][2] = __expf(S[nb][2] - mnb);
            S[nb][3] = __expf(S[nb][3] - mnb);
            sum_a += S[nb][0] + S[nb][1];
            sum_b += S[nb][2] + S[nb][3];
        }
        sum_a += __shfl_xor_sync(0xffffffffu, sum_a, 1);
        sum_a += __shfl_xor_sync(0xffffffffu, sum_a, 2);
        sum_b += __shfl_xor_sync(0xffffffffu, sum_b, 1);
        sum_b += __shfl_xor_sync(0xffffffffu, sum_b, 2);
        l_a = l_a * ca + sum_a;  l_b = l_b * cb + sum_b;
        m_a = mna;  m_b = mnb;
#pragma unroll
        for (int nb = 0; nb < 8; nb++) {
            O[nb][0] *= ca; O[nb][1] *= ca;
            O[nb][2] *= cb; O[nb][3] *= cb;
        }
        // P.V: P A-frags from S C-frags; Vt[d][k] -> float2 B-frags
#pragma unroll
        for (int kb = 0; kb < 8; kb++) {
            unsigned pa[4] = { cvt_tf32(S[kb][0]), cvt_tf32(S[kb][2]),
                               cvt_tf32(S[kb][1]), cvt_tf32(S[kb][3]) };
#pragma unroll
            for (int nb = 0; nb < 8; nb++) {
                float2 tb = *(const float2*)&vs[(nb * 8 + g) * 72 + kb * 8 + 2 * tig];
                mma8(O[nb], pa, __float_as_uint(tb.x), __float_as_uint(tb.y));
            }
        }
        __syncthreads();
        if (kt + 2 < 16) stage(b, kt + 2);
    }

    float ia = 1.f / l_a, ib = 1.f / l_b;
    int t0 = qrow + g, t1 = t0 + 8;
#pragma unroll
    for (int nb = 0; nb < 8; nb++) {
        int d = h * 64 + nb * 8 + 2 * tig;
        *(float2*)(g_O + (size_t)(b_ * 1024 + t0) * 512 + d) =
            make_float2(cvt_tf32f(O[nb][0] * ia), cvt_tf32f(O[nb][1] * ia));
        *(float2*)(g_O + (size_t)(b_ * 1024 + t1) * 512 + d) =
            make_float2(cvt_tf32f(O[nb][2] * ib), cvt_tf32f(O[nb][3] * ib));
    }
}

// ---------------------------------------------------------------------------
extern "C" void kernel_launch(void* const* d_in, const int* in_sizes, int n_in,
                              void* d_out, int out_size)
{
    (void)in_sizes; (void)n_in; (void)out_size;
    const float* x    = (const float*)d_in[0];
    const float* posk = (const float*)d_in[1];
    const float* Wq = (const float*)d_in[3];
    const float* bq = (const float*)d_in[4];
    const float* Wk = (const float*)d_in[5];
    const float* bk = (const float*)d_in[6];
    const float* Wv = (const float*)d_in[7];
    const float* bv = (const float*)d_in[8];
    const float* Wo = (const float*)d_in[9];
    const float* bo = (const float*)d_in[10];
    float* out = (float*)d_out;

    float *qp, *kp, *vp, *op, *wtp, *xtp;
    cudaGetSymbolAddress((void**)&qp, g_Q);
    cudaGetSymbolAddress((void**)&kp, g_K);
    cudaGetSymbolAddress((void**)&vp, g_V);
    cudaGetSymbolAddress((void**)&op, g_O);
    cudaGetSymbolAddress((void**)&wtp, g_Wt);
    cudaGetSymbolAddress((void**)&xtp, g_xt);

    cudaFuncSetAttribute(qkv_kernel,
                         cudaFuncAttributeMaxDynamicSharedMemorySize, PROJ_SMEM);
    cudaFuncSetAttribute(oproj_kernel,
                         cudaFuncAttributeMaxDynamicSharedMemorySize, PROJ_SMEM);
    cudaFuncSetAttribute(pos_kernel,
                         cudaFuncAttributeMaxDynamicSharedMemorySize, POS_SMEM);
    cudaFuncSetAttribute(attn_kernel,
                         cudaFuncAttributeMaxDynamicSharedMemorySize, ATTN_SMEM);

    prep_kernel<<<dim3(16, 16, 5), dim3(32, 8)>>>(Wq, Wk, Wv, Wo, x);
    qkv_kernel<<<dim3(4, 32, 3), 256, PROJ_SMEM>>>(xtp, wtp, bq, bk, bv, qp, kp, vp);
    pos_kernel<<<dim3(8, 128), 256, POS_SMEM>>>(posk);
    attn_kernel<<<dim3(8, 32), 256, ATTN_SMEM>>>();
    oproj_kernel<<<dim3(4, 32), 256, PROJ_SMEM>>>(op, wtp + 3 * 262144, bo, out);
}

// round 7
// speedup vs baseline: 4.6591x; 1.3941x over previous
#include <cuda_runtime.h>
#include <cuda_fp16.h>
#include <cstdint>

// ---------------------------------------------------------------------------
// MultiHeadSelfAttention + relative position — fp16-input mma.sync (fp32
// accum) everywhere; fp16 == tf32 mantissa so precision is unchanged.
//   K0: prep — transpose weights -> fp16 Wt, round x -> fp16
//   K1: QKV projection fp16 GEMM (Q,K: [bh][t][d]; V: [bh][d][t] fp16)
//   K2: S_pos[bh][q][k] tf32 mma (pos_k fp32 streamed once), fp16 output
//   K3: flash attention, all fp16 mma, K/V/Spos cp.async ring
//   K4: output projection fp16 GEMM -> fp32 out
// ---------------------------------------------------------------------------

#define NBH 32
#define TSEQ 1024
#define DH 64

__device__ __align__(16) __half g_Qh[NBH * TSEQ * DH];       // [bh][t][d]
__device__ __align__(16) __half g_Kh[NBH * TSEQ * DH];       // [bh][t][d]
__device__ __align__(16) __half g_Vh[NBH * TSEQ * DH];       // [bh][d][t] !
__device__ __align__(16) __half g_Oh[4096 * 512];            // [t][n]
__device__ __align__(16) __half g_SposH[(size_t)NBH * TSEQ * TSEQ]; // [bh][q][k]
__device__ __align__(16) __half g_Wth[4 * 512 * 512];        // W^T fp16
__device__ __align__(16) __half g_xh[4096 * 512];            // x fp16

// ---------------- helpers ---------------------------------------------------
__device__ __forceinline__ uint32_t smem_u32(const void* p) {
    uint32_t a;
    asm("{ .reg .u64 t; cvta.to.shared.u64 t, %1; cvt.u32.u64 %0, t; }"
        : "=r"(a) : "l"(p));
    return a;
}
__device__ __forceinline__ void cp_async16(uint32_t dst, const void* src) {
    asm volatile("cp.async.cg.shared.global [%0], [%1], 16;"
                 :: "r"(dst), "l"(src));
}
__device__ __forceinline__ void cp_commit() {
    asm volatile("cp.async.commit_group;");
}
template <int N> __device__ __forceinline__ void cp_wait() {
    asm volatile("cp.async.wait_group %0;" :: "n"(N));
}
__device__ __forceinline__ unsigned cvt_tf32(float x) {
    unsigned u; asm("cvt.rna.tf32.f32 %0, %1;" : "=r"(u) : "f"(x)); return u;
}
__device__ __forceinline__ unsigned pack_h2(float x, float y) {
    __half2 h = __floats2half2_rn(x, y);
    return *(unsigned*)&h;
}
__device__ __forceinline__ void mma16(float* c, const unsigned* a,
                                      unsigned b0, unsigned b1) {
    asm volatile(
        "mma.sync.aligned.m16n8k16.row.col.f32.f16.f16.f32 "
        "{%0,%1,%2,%3}, {%4,%5,%6,%7}, {%8,%9}, {%0,%1,%2,%3};\n"
        : "+f"(c[0]), "+f"(c[1]), "+f"(c[2]), "+f"(c[3])
        : "r"(a[0]), "r"(a[1]), "r"(a[2]), "r"(a[3]), "r"(b0), "r"(b1));
}
__device__ __forceinline__ void mma8t(float* c, const unsigned* a,
                                      unsigned b0, unsigned b1) {
    asm volatile(
        "mma.sync.aligned.m16n8k8.row.col.f32.tf32.tf32.f32 "
        "{%0,%1,%2,%3}, {%4,%5,%6,%7}, {%8,%9}, {%0,%1,%2,%3};\n"
        : "+f"(c[0]), "+f"(c[1]), "+f"(c[2]), "+f"(c[3])
        : "r"(a[0]), "r"(a[1]), "r"(a[2]), "r"(a[3]), "r"(b0), "r"(b1));
}

// ---------------------------------------------------------------------------
// K0: prep. z<4: transpose weight z -> fp16 Wt. z==4: x -> fp16.
// grid (16,16,5), block (32,8).
// ---------------------------------------------------------------------------
__global__ __launch_bounds__(256) void prep_kernel(
    const float* __restrict__ W0, const float* __restrict__ W1,
    const float* __restrict__ W2, const float* __restrict__ W3,
    const float* __restrict__ x)
{
    int tx = threadIdx.x, ty = threadIdx.y;
    if (blockIdx.z == 4) {
        int t = ty * 32 + tx;
        size_t base = ((size_t)blockIdx.y * 16 + blockIdx.x) * 8192;
#pragma unroll
        for (int j = 0; j < 8; j++) {
            size_t i = base + ((size_t)(t + j * 256) << 2);
            float4 v = *(const float4*)(x + i);
            *(__half2*)(g_xh + i)     = __floats2half2_rn(v.x, v.y);
            *(__half2*)(g_xh + i + 2) = __floats2half2_rn(v.z, v.w);
        }
        return;
    }
    __shared__ float t[32][33];
    const float* W = W0;
    if (blockIdx.z == 1) W = W1;
    else if (blockIdx.z == 2) W = W2;
    else if (blockIdx.z == 3) W = W3;
    __half* dst = g_Wth + (size_t)blockIdx.z * 512 * 512;
    int x0 = blockIdx.x * 32 + tx, y0 = blockIdx.y * 32 + ty;
#pragma unroll
    for (int dy = 0; dy < 32; dy += 8)
        t[ty + dy][tx] = W[(size_t)(y0 + dy) * 512 + x0];
    __syncthreads();
    int x2 = blockIdx.y * 32 + tx, y2 = blockIdx.x * 32 + ty;
#pragma unroll
    for (int dy = 0; dy < 32; dy += 8)
        dst[(size_t)(y2 + dy) * 512 + x2] = __float2half_rn(t[tx][ty + dy]);
}

// ---------------------------------------------------------------------------
// fp16 projection GEMM: C[4096x512] = A @ Wt^T + bias. CTA 128x128, BK=32,
// 8 warps (warp 32x64), double-buffered cp.async. dyn smem 40960 B.
// permute: 0 = row-major fp32 out; 1 = [bh][t][d] fp16 (Q,K); 2 = [bh][d][t]
// fp16 (V); 3 = row-major fp16 (unused)
// ---------------------------------------------------------------------------
#define PROJ_SMEM 40960

__device__ __forceinline__ void proj_body(
    const __half* __restrict__ A, const __half* __restrict__ Wt,
    const float* __restrict__ bias, void* __restrict__ outv, int permute)
{
    extern __shared__ char smc[];
    __half* As = (__half*)smc;                  // [2][128*40]
    __half* Bs = (__half*)(smc + 2 * 10240);    // [2][128*40]
    const uint32_t asu = smem_u32(As), bsu = smem_u32(Bs);
    const int tid = threadIdx.x;
    const int lane = tid & 31, g = lane >> 2, tig = lane & 3;
    const int warp = tid >> 5, wm = warp >> 1, wn = warp & 1;
    const int mbase = blockIdx.y * 128, nbase = blockIdx.x * 128;

    float C[2][8][4];
#pragma unroll
    for (int mb = 0; mb < 2; mb++)
#pragma unroll
        for (int nb = 0; nb < 8; nb++)
#pragma unroll
            for (int i = 0; i < 4; i++) C[mb][nb][i] = 0.f;

    auto stage = [&](int buf, int k0) {
        uint32_t ab = asu + buf * 10240, bb = bsu + buf * 10240;
#pragma unroll
        for (int i = 0; i < 2; i++) {
            int c = tid + i * 256;
            int m = c >> 2, p = c & 3;
            cp_async16(ab + m * 80 + p * 16,
                       A + (size_t)(mbase + m) * 512 + k0 + p * 8);
            cp_async16(bb + m * 80 + p * 16,
                       Wt + (size_t)(nbase + m) * 512 + k0 + p * 8);
        }
        cp_commit();
    };
    stage(0, 0);
    stage(1, 32);

    for (int s = 0; s < 16; s++) {
        int b = s & 1;
        if (s == 15) cp_wait<0>(); else cp_wait<1>();
        __syncthreads();
        const __half* as = As + b * 5120;
        const __half* bs = Bs + b * 5120;
#pragma unroll
        for (int kk = 0; kk < 2; kk++) {
            unsigned a[2][4];
#pragma unroll
            for (int mb = 0; mb < 2; mb++) {
                int r = wm * 32 + mb * 16 + g;
                a[mb][0] = *(const unsigned*)&as[r * 40 + kk * 16 + 2 * tig];
                a[mb][1] = *(const unsigned*)&as[(r + 8) * 40 + kk * 16 + 2 * tig];
                a[mb][2] = *(const unsigned*)&as[r * 40 + kk * 16 + 2 * tig + 8];
                a[mb][3] = *(const unsigned*)&as[(r + 8) * 40 + kk * 16 + 2 * tig + 8];
            }
#pragma unroll
            for (int nb = 0; nb < 8; nb++) {
                const __half* bp = &bs[(wn * 64 + nb * 8 + g) * 40 + kk * 16 + 2 * tig];
                unsigned b0 = *(const unsigned*)bp;
                unsigned b1 = *(const unsigned*)(bp + 8);
                mma16(C[0][nb], a[0], b0, b1);
                mma16(C[1][nb], a[1], b0, b1);
            }
        }
        __syncthreads();
        if (s + 2 < 16) stage(b, (s + 2) * 32);
    }

#pragma unroll
    for (int nb = 0; nb < 8; nb++) {
        int ncol = wn * 64 + nb * 8 + 2 * tig;
        float2 bb = *(const float2*)(bias + nbase + ncol);
#pragma unroll
        for (int mb = 0; mb < 2; mb++) {
            int r0 = mbase + wm * 32 + mb * 16 + g;
            int r1 = r0 + 8;
            float2 v0 = make_float2(C[mb][nb][0] + bb.x, C[mb][nb][1] + bb.y);
            float2 v1 = make_float2(C[mb][nb][2] + bb.x, C[mb][nb][3] + bb.y);
            if (permute == 1) {
                __half* out = (__half*)outv;
                int h = (nbase >> 6) + wn;
                int d = nb * 8 + 2 * tig;
                *(__half2*)(out + (((size_t)((r0 >> 10) * 8 + h) * 1024 + (r0 & 1023)) << 6) + d)
                    = __floats2half2_rn(v0.x, v0.y);
                *(__half2*)(out + (((size_t)((r1 >> 10) * 8 + h) * 1024 + (r1 & 1023)) << 6) + d)
                    = __floats2half2_rn(v1.x, v1.y);
            } else if (permute == 2) {
                __half* out = (__half*)outv;
                int h = (nbase >> 6) + wn;
                int d = nb * 8 + 2 * tig;
                size_t base = ((size_t)((r0 >> 10) * 8 + h) * 64 + d) * 1024;
                int t0 = r0 & 1023, t1 = r1 & 1023;
                out[base + t0]        = __float2half_rn(v0.x);
                out[base + 1024 + t0] = __float2half_rn(v0.y);
                out[base + t1]        = __float2half_rn(v1.x);
                out[base + 1024 + t1] = __float2half_rn(v1.y);
            } else {
                float* out = (float*)outv;
                *(float2*)(out + (size_t)r0 * 512 + nbase + ncol) = v0;
                *(float2*)(out + (size_t)r1 * 512 + nbase + ncol) = v1;
            }
        }
    }
}

__global__ __launch_bounds__(256, 2) void qkv_kernel(
    const float* __restrict__ bq, const float* __restrict__ bk,
    const float* __restrict__ bv)
{
    const __half* wt = g_Wth; const float* bias = bq;
    void* out = g_Qh; int perm = 1;
    if (blockIdx.z == 1) { wt = g_Wth + 262144;      bias = bk; out = g_Kh; }
    else if (blockIdx.z == 2) { wt = g_Wth + 524288; bias = bv; out = g_Vh; perm = 2; }
    proj_body(g_xh, wt, bias, out, perm);
}
__global__ __launch_bounds__(256, 2) void oproj_kernel(
    const float* __restrict__ bias, float* __restrict__ out)
{
    proj_body(g_Oh, g_Wth + 3 * 262144, bias, out, 0);
}

// ---------------------------------------------------------------------------
// K2: S_pos. CTA = (k-chunk 128, q-group of 8). 256 thr, 8 warps (16bh x 32k).
// A = fp16 Q (lossless in tf32), B = fp32 pos_k (cvt.rna in reg), tf32 mma.
// Output fp16. dyn smem 82944 B (2 CTAs/SM).
// ---------------------------------------------------------------------------
#define POS_SMEM 82944

__global__ __launch_bounds__(256, 2) void pos_kernel(const float* __restrict__ pos_k)
{
    extern __shared__ char smc[];
    __half* As = (__half*)smc;                 // [2][32*72]
    float*  Bs = (float*)(smc + 2 * 4608);     // [2][128*72]
    const uint32_t asu = smem_u32(As), bsu = smem_u32(Bs);
    const int tid = threadIdx.x;
    const int lane = tid & 31, g = lane >> 2, tig = lane & 3;
    const int w = tid >> 5, wm = w >> 2, wn = w & 3;
    const int q0 = blockIdx.y * 8, kc = blockIdx.x * 128;

    auto stage = [&](int buf, int qi) {
        int q = q0 + qi;
        {
            int r = tid >> 3, p = tid & 7;
            cp_async16(asu + buf * 4608 + r * 144 + p * 16,
                       g_Qh + ((size_t)r * 1024 + q) * 64 + p * 8);
        }
#pragma unroll
        for (int i = 0; i < 8; i++) {
            int c = tid + i * 256;
            int r = c >> 4, p = c & 15;
            cp_async16(bsu + buf * 36864 + r * 288 + p * 16,
                       pos_k + ((size_t)q * 1024 + kc + r) * 64 + p * 4);
        }
        cp_commit();
    };
    stage(0, 0);
    stage(1, 1);

    for (int i = 0; i < 8; i++) {
        int b = i & 1;
        if (i == 7) cp_wait<0>(); else cp_wait<1>();
        __syncthreads();
        const __half* as = As + b * 2304;
        const float*  bs = Bs + b * 9216;

        float C[4][4];
#pragma unroll
        for (int nb = 0; nb < 4; nb++)
#pragma unroll
            for (int j = 0; j < 4; j++) C[nb][j] = 0.f;

#pragma unroll
        for (int kk = 0; kk < 8; kk++) {
            unsigned a[4];
            int r = wm * 16 + g;
            float2 t0 = __half22float2(*(const __half2*)&as[r * 72 + kk * 8 + 2 * tig]);
            float2 t1 = __half22float2(*(const __half2*)&as[(r + 8) * 72 + kk * 8 + 2 * tig]);
            a[0] = __float_as_uint(t0.x); a[2] = __float_as_uint(t0.y);
            a[1] = __float_as_uint(t1.x); a[3] = __float_as_uint(t1.y);
#pragma unroll
            for (int nb = 0; nb < 4; nb++) {
                float2 tb = *(const float2*)&bs[(wn * 32 + nb * 8 + g) * 72 + kk * 8 + 2 * tig];
                mma8t(C[nb], a, cvt_tf32(tb.x), cvt_tf32(tb.y));
            }
        }

        int q = q0 + i;
#pragma unroll
        for (int nb = 0; nb < 4; nb++) {
            int k = kc + wn * 32 + nb * 8 + 2 * tig;
            int bh0 = wm * 16 + g;
            *(__half2*)(g_SposH + ((size_t)bh0 * 1024 + q) * 1024 + k)
                = __floats2half2_rn(C[nb][0], C[nb][1]);
            *(__half2*)(g_SposH + ((size_t)(bh0 + 8) * 1024 + q) * 1024 + k)
                = __floats2half2_rn(C[nb][2], C[nb][3]);
        }
        __syncthreads();
        if (i + 2 < 8) stage(b, i + 2);
    }
}

// ---------------------------------------------------------------------------
// K3: flash attention, all fp16 mma. CTA = (bh, 128-q tile), 8 warps.
// 2-stage cp.async ring staging K[k][d], V[d][k], Spos[q][k] (all fp16).
// dyn smem 73728 B (2 CTAs/SM).
// ---------------------------------------------------------------------------
#define ATTN_SMEM 73728

__global__ __launch_bounds__(256, 2) void attn_kernel()
{
    extern __shared__ char smc[];
    __half* Ks = (__half*)smc;                 // [2][64*72]   [k][d]
    __half* Vs = (__half*)(smc + 2 * 9216);    // [2][64*72]   [d][k]
    __half* Ss = (__half*)(smc + 4 * 9216);    // [2][128*72]  [q][k]
    const uint32_t ksu = smem_u32(Ks), vsu = smem_u32(Vs), ssu = smem_u32(Ss);
    const int tid = threadIdx.x;
    const int lane = tid & 31, g = lane >> 2, tig = lane & 3;
    const int w = tid >> 5;
    const int bh = blockIdx.y, qt = blockIdx.x;
    const int b_ = bh >> 3, h = bh & 7;
    const int qrow = qt * 128 + w * 16;

    unsigned Qa[4][4];
    {
        const __half* qb = g_Qh + ((size_t)bh * 1024 + qrow) * 64;
#pragma unroll
        for (int kk = 0; kk < 4; kk++) {
            Qa[kk][0] = *(const unsigned*)(qb + g * 64 + kk * 16 + 2 * tig);
            Qa[kk][1] = *(const unsigned*)(qb + (g + 8) * 64 + kk * 16 + 2 * tig);
            Qa[kk][2] = *(const unsigned*)(qb + g * 64 + kk * 16 + 2 * tig + 8);
            Qa[kk][3] = *(const unsigned*)(qb + (g + 8) * 64 + kk * 16 + 2 * tig + 8);
        }
    }

    auto stage = [&](int buf, int kt) {
        const __half* kbase = g_Kh + ((size_t)bh * 1024 + kt * 64) * 64;
        const __half* vbase = g_Vh + ((size_t)bh * 64) * 1024 + kt * 64;
        const __half* sbase = g_SposH + ((size_t)(bh * 1024 + qt * 128)) * 1024 + kt * 64;
#pragma unroll
        for (int i = 0; i < 2; i++) {
            int c = tid + i * 256;
            int r = c >> 3, p = c & 7;
            cp_async16(ksu + buf * 9216 + r * 144 + p * 16, kbase + r * 64 + p * 8);
            cp_async16(vsu + buf * 9216 + r * 144 + p * 16,
                       vbase + (size_t)r * 1024 + p * 8);
        }
#pragma unroll
        for (int i = 0; i < 4; i++) {
            int c = tid + i * 256;
            int r = c >> 3, p = c & 7;
            cp_async16(ssu + buf * 18432 + r * 144 + p * 16,
                       sbase + (size_t)r * 1024 + p * 8);
        }
        cp_commit();
    };
    stage(0, 0);
    stage(1, 1);

    float O[8][4];
#pragma unroll
    for (int nb = 0; nb < 8; nb++)
#pragma unroll
        for (int i = 0; i < 4; i++) O[nb][i] = 0.f;
    float m_a = -1e30f, m_b = -1e30f, l_a = 0.f, l_b = 0.f;

    for (int kt = 0; kt < 16; kt++) {
        int b = kt & 1;
        if (kt == 15) cp_wait<0>(); else cp_wait<1>();
        __syncthreads();

        const __half* ks = Ks + b * 4608;
        const __half* vs = Vs + b * 4608;
        const __half* ss = Ss + b * 9216;

        float S[8][4];
#pragma unroll
        for (int nb = 0; nb < 8; nb++)
#pragma unroll
            for (int i = 0; i < 4; i++) S[nb][i] = 0.f;
#pragma unroll
        for (int kk = 0; kk < 4; kk++)
#pragma unroll
            for (int nb = 0; nb < 8; nb++) {
                const __half* bp = &ks[(nb * 8 + g) * 72 + kk * 16 + 2 * tig];
                mma16(S[nb], Qa[kk], *(const unsigned*)bp, *(const unsigned*)(bp + 8));
            }

        float ra = -1e30f, rb = -1e30f;
#pragma unroll
        for (int nb = 0; nb < 8; nb++) {
            float2 sa = __half22float2(
                *(const __half2*)&ss[(w * 16 + g) * 72 + nb * 8 + 2 * tig]);
            float2 sb = __half22float2(
                *(const __half2*)&ss[(w * 16 + g + 8) * 72 + nb * 8 + 2 * tig]);
            S[nb][0] = (S[nb][0] + sa.x) * 0.125f;
            S[nb][1] = (S[nb][1] + sa.y) * 0.125f;
            S[nb][2] = (S[nb][2] + sb.x) * 0.125f;
            S[nb][3] = (S[nb][3] + sb.y) * 0.125f;
            ra = fmaxf(ra, fmaxf(S[nb][0], S[nb][1]));
            rb = fmaxf(rb, fmaxf(S[nb][2], S[nb][3]));
        }
        ra = fmaxf(ra, __shfl_xor_sync(0xffffffffu, ra, 1));
        ra = fmaxf(ra, __shfl_xor_sync(0xffffffffu, ra, 2));
        rb = fmaxf(rb, __shfl_xor_sync(0xffffffffu, rb, 1));
        rb = fmaxf(rb, __shfl_xor_sync(0xffffffffu, rb, 2));
        float mna = fmaxf(m_a, ra), mnb = fmaxf(m_b, rb);
        float ca = __expf(m_a - mna), cb = __expf(m_b - mnb);
        float sum_a = 0.f, sum_b = 0.f;
#pragma unroll
        for (int nb = 0; nb < 8; nb++) {
            S[nb][0] = __expf(S[nb][0] - mna);
            S[nb][1] = __expf(S[nb][1] - mna);
            S[nb][2] = __expf(S[nb][2] - mnb);
            S[nb][3] = __expf(S[nb][3] - mnb);
            sum_a += S[nb][0] + S[nb][1];
            sum_b += S[nb][2] + S[nb][3];
        }
        sum_a += __shfl_xor_sync(0xffffffffu, sum_a, 1);
        sum_a += __shfl_xor_sync(0xffffffffu, sum_a, 2);
        sum_b += __shfl_xor_sync(0xffffffffu, sum_b, 1);
        sum_b += __shfl_xor_sync(0xffffffffu, sum_b, 2);
        l_a = l_a * ca + sum_a;  l_b = l_b * cb + sum_b;
        m_a = mna;  m_b = mnb;
#pragma unroll
        for (int nb = 0; nb < 8; nb++) {
            O[nb][0] *= ca; O[nb][1] *= ca;
            O[nb][2] *= cb; O[nb][3] *= cb;
        }
        // P.V: P A-frags packed straight from S C-frags (k16 = two k8 blocks)
#pragma unroll
        for (int kb = 0; kb < 4; kb++) {
            unsigned pa[4] = {
                pack_h2(S[2 * kb][0],     S[2 * kb][1]),
                pack_h2(S[2 * kb][2],     S[2 * kb][3]),
                pack_h2(S[2 * kb + 1][0], S[2 * kb + 1][1]),
                pack_h2(S[2 * kb + 1][2], S[2 * kb + 1][3]) };
#pragma unroll
            for (int nb = 0; nb < 8; nb++) {
                const __half* bp = &vs[(nb * 8 + g) * 72 + kb * 16 + 2 * tig];
                mma16(O[nb], pa, *(const unsigned*)bp, *(const unsigned*)(bp + 8));
            }
        }
        __syncthreads();
        if (kt + 2 < 16) stage(b, kt + 2);
    }

    float ia = 1.f / l_a, ib = 1.f / l_b;
    int t0 = qrow + g, t1 = t0 + 8;
#pragma unroll
    for (int nb = 0; nb < 8; nb++) {
        int d = h * 64 + nb * 8 + 2 * tig;
        *(__half2*)(g_Oh + (size_t)(b_ * 1024 + t0) * 512 + d)
            = __floats2half2_rn(O[nb][0] * ia, O[nb][1] * ia);
        *(__half2*)(g_Oh + (size_t)(b_ * 1024 + t1) * 512 + d)
            = __floats2half2_rn(O[nb][2] * ib, O[nb][3] * ib);
    }
}

// ---------------------------------------------------------------------------
extern "C" void kernel_launch(void* const* d_in, const int* in_sizes, int n_in,
                              void* d_out, int out_size)
{
    (void)in_sizes; (void)n_in; (void)out_size;
    const float* x    = (const float*)d_in[0];
    const float* posk = (const float*)d_in[1];
    const float* Wq = (const float*)d_in[3];
    const float* bq = (const float*)d_in[4];
    const float* Wk = (const float*)d_in[5];
    const float* bk = (const float*)d_in[6];
    const float* Wv = (const float*)d_in[7];
    const float* bv = (const float*)d_in[8];
    const float* Wo = (const float*)d_in[9];
    const float* bo = (const float*)d_in[10];
    float* out = (float*)d_out;

    cudaFuncSetAttribute(qkv_kernel,
                         cudaFuncAttributeMaxDynamicSharedMemorySize, PROJ_SMEM);
    cudaFuncSetAttribute(oproj_kernel,
                         cudaFuncAttributeMaxDynamicSharedMemorySize, PROJ_SMEM);
    cudaFuncSetAttribute(pos_kernel,
                         cudaFuncAttributeMaxDynamicSharedMemorySize, POS_SMEM);
    cudaFuncSetAttribute(attn_kernel,
                         cudaFuncAttributeMaxDynamicSharedMemorySize, ATTN_SMEM);

    prep_kernel<<<dim3(16, 16, 5), dim3(32, 8)>>>(Wq, Wk, Wv, Wo, x);
    qkv_kernel<<<dim3(4, 32, 3), 256, PROJ_SMEM>>>(bq, bk, bv);
    pos_kernel<<<dim3(8, 128), 256, POS_SMEM>>>(posk);
    attn_kernel<<<dim3(8, 32), 256, ATTN_SMEM>>>();
    oproj_kernel<<<dim3(4, 32), 256, PROJ_SMEM>>>(bo, out);
}